// round 2
// baseline (speedup 1.0000x reference)
#include <cuda_runtime.h>
#include <math.h>

#define H 4
#define Bb 32
#define Tt 1000
#define EPROJS 1024
#define DUNITS 1024
#define DKk 512
#define DVv 512
#define CC 100
#define CP 112            // conv channels padded to multiple of 16
#define MM (Bb*Tt)        // 32000 rows
#define NBLK 8            // 512 / 64 column blocks in energy kernel

// ---------------- scratch (static device globals; no allocation) ----------------
__device__ float g_conv_feat[H*MM*CP];     // [H, B*T, 112] padded conv features
__device__ float g_Wattp[H*CP*DKk];        // [H, 112, 512] zero-padded Watt
__device__ float g_q[H*Bb*DKk];            // [H, B, 512]
__device__ float g_epart[NBLK*H*MM];       // per-colblock partial energies
__device__ float g_e[H*MM];                // energies
__device__ float g_w[H*MM];                // softmax weights
__device__ float g_ctx[H*Bb*EPROJS];       // [H, B, 1024] = sum_t w * enc
__device__ float g_cv[H*Bb*DVv];           // [H, B, 512]  = ctx @ Wv

// ---------------- pad Watt into [H,112,512] ----------------
__global__ void wattp_kernel(const float* __restrict__ Watt){
  int idx = blockIdx.x*blockDim.x + threadIdx.x;
  if (idx >= H*CP*DKk) return;
  int n = idx % DKk; int r = (idx / DKk) % CP; int h = idx / (DKk*CP);
  g_Wattp[idx] = (r < CC) ? Watt[(h*CC + r)*DKk + n] : 0.f;
}

// ---------------- location conv: att_prev -> conv_feat [H,B,T,112] ----------------
__global__ void conv_kernel(const float* __restrict__ ap,
                            const float* __restrict__ w0, const float* __restrict__ w1,
                            const float* __restrict__ w2, const float* __restrict__ w3){
  int h = blockIdx.z, b = blockIdx.y, t0 = blockIdx.x*128;
  int F = 25*(h+1);            // FILTS = 25,50,75,100
  int K = 2*F+1;
  const float* wb = (h==0)?w0:(h==1)?w1:(h==2)?w2:w3;
  __shared__ float sm[128 + 200];
  const float* arow = ap + (h*Bb + b)*Tt;
  for (int i = threadIdx.x; i < 128 + 2*F; i += 128){
    int tt = t0 - F + i;
    sm[i] = (tt >= 0 && tt < Tt) ? arow[tt] : 0.f;
  }
  __syncthreads();
  int t = t0 + (int)threadIdx.x;
  if (t >= Tt) return;
  float* outp = g_conv_feat + ((size_t)(h*Bb + b)*Tt + t)*CP;
  for (int c = 0; c < CC; c++){
    const float* wr = wb + c*K;
    float s = 0.f;
    #pragma unroll 4
    for (int tau = 0; tau < K; tau++)
      s += sm[threadIdx.x + tau] * wr[tau];
    outp[c] = s;
  }
  #pragma unroll
  for (int c = CC; c < CP; c++) outp[c] = 0.f;
}

// ---------------- q = dec_z @ Wq + bq ----------------
__global__ void q_kernel(const float* __restrict__ dec_z, const float* __restrict__ Wq,
                         const float* __restrict__ bq){
  int idx = blockIdx.x*blockDim.x + threadIdx.x;
  if (idx >= H*Bb*DKk) return;
  int n = idx % DKk; int b = (idx / DKk) % Bb; int h = idx / (DKk*Bb);
  const float* z  = dec_z + b*DUNITS;
  const float* wp = Wq + (size_t)h*DUNITS*DKk + n;
  float s = bq[h*DKk + n];
  #pragma unroll 4
  for (int d = 0; d < DUNITS; d++) s += z[d]*wp[(size_t)d*DKk];
  g_q[idx] = s;
}

// ---------------- fused energy GEMM: e_part = sum_cols tanh(enc@Wk + cf@Watt + q)*g_w --------
// Tile 64x64, 256 threads, 4x4 register blocking, K-dim = 1024 (enc/Wk) + 112 (conv/Watt)
__global__ __launch_bounds__(256) void energy_kernel(
    const float* __restrict__ enc, const float* __restrict__ Wk,
    const float* __restrict__ gw){
  int h  = blockIdx.z;
  int m0 = blockIdx.y * 64;
  int n0 = blockIdx.x * 64;
  const float* A2 = g_conv_feat + (size_t)h*MM*CP;
  const float* B1 = Wk + (size_t)h*EPROJS*DKk;
  const float* B2 = g_Wattp + (size_t)h*CP*DKk;

  __shared__ float As[16][68];   // [k][m], padded to reduce STS conflicts
  __shared__ float Bs[16][64];   // [k][n]

  int tid = threadIdx.x;
  int ty = tid >> 4, tx = tid & 15;

  float acc[4][4];
  #pragma unroll
  for (int i=0;i<4;i++){ acc[i][0]=0.f; acc[i][1]=0.f; acc[i][2]=0.f; acc[i][3]=0.f; }

  int lm  = tid >> 2;         // 0..63 (A load row)
  int lk4 = (tid & 3) * 4;    // 0,4,8,12 (A load k)
  int lkk = tid >> 4;         // 0..15 (B load k)
  int ln4 = (tid & 15) * 4;   // B load n

  for (int kc = 0; kc < 71; kc++){
    float4 av, bv;
    if (kc < 64){
      av = *(const float4*)(enc + (size_t)(m0+lm)*EPROJS + kc*16 + lk4);
      bv = *(const float4*)(B1  + (size_t)(kc*16 + lkk)*DKk + n0 + ln4);
    } else {
      av = *(const float4*)(A2 + (size_t)(m0+lm)*CP + (kc-64)*16 + lk4);
      bv = *(const float4*)(B2 + (size_t)((kc-64)*16 + lkk)*DKk + n0 + ln4);
    }
    __syncthreads();
    As[lk4+0][lm]=av.x; As[lk4+1][lm]=av.y; As[lk4+2][lm]=av.z; As[lk4+3][lm]=av.w;
    *(float4*)&Bs[lkk][ln4] = bv;
    __syncthreads();
    #pragma unroll
    for (int kk=0;kk<16;kk++){
      float4 a = *(const float4*)&As[kk][ty*4];
      float4 b = *(const float4*)&Bs[kk][tx*4];
      acc[0][0] += a.x*b.x; acc[0][1] += a.x*b.y; acc[0][2] += a.x*b.z; acc[0][3] += a.x*b.w;
      acc[1][0] += a.y*b.x; acc[1][1] += a.y*b.y; acc[1][2] += a.y*b.z; acc[1][3] += a.y*b.w;
      acc[2][0] += a.z*b.x; acc[2][1] += a.z*b.y; acc[2][2] += a.z*b.z; acc[2][3] += a.z*b.w;
      acc[3][0] += a.w*b.x; acc[3][1] += a.w*b.y; acc[3][2] += a.w*b.z; acc[3][3] += a.w*b.w;
    }
  }

  // epilogue: add q, tanh, dot with g_w, reduce across the 16 tx lanes of each row
  float gwv[4];
  #pragma unroll
  for (int j=0;j<4;j++) gwv[j] = gw[h*DKk + n0 + tx*4 + j];
  #pragma unroll
  for (int i=0;i<4;i++){
    int row = m0 + ty*4 + i;
    int b   = row / Tt;
    const float* qp = g_q + (size_t)(h*Bb + b)*DKk + n0 + tx*4;
    float p = 0.f;
    #pragma unroll
    for (int j=0;j<4;j++) p += tanhf(acc[i][j] + qp[j]) * gwv[j];
    #pragma unroll
    for (int o=8;o;o>>=1) p += __shfl_xor_sync(0xffffffffu, p, o);
    if (tx == 0)
      g_epart[(size_t)blockIdx.x*(H*MM) + (size_t)h*MM + row] = p;
  }
}

// ---------------- deterministic reduction of column-block partials + g_b -----------
__global__ void ereduce_kernel(const float* __restrict__ gb){
  int idx = blockIdx.x*blockDim.x + threadIdx.x;
  if (idx >= H*MM) return;
  int h = idx / MM;
  float s = gb[h];
  #pragma unroll
  for (int j=0;j<NBLK;j++) s += g_epart[(size_t)j*(H*MM) + idx];
  g_e[idx] = s;
}

// ---------------- softmax over T per (h,b); also writes w output ----------------
__global__ void softmax_kernel(float* __restrict__ wout){
  __shared__ float red[8];
  int hb = blockIdx.x;                 // h*B + b
  const float scale = 0.04419417382415922f;  // 1/sqrt(512)
  const float* ep = g_e + (size_t)hb*Tt;
  int tid = threadIdx.x;
  float v[4];
  float mx = -1e30f;
  #pragma unroll
  for (int i=0;i<4;i++){
    int t = tid + i*256;
    v[i] = (t < Tt) ? ep[t]*scale : -1e30f;
    mx = fmaxf(mx, v[i]);
  }
  #pragma unroll
  for (int o=16;o;o>>=1) mx = fmaxf(mx, __shfl_xor_sync(0xffffffffu, mx, o));
  if ((tid&31)==0) red[tid>>5] = mx;
  __syncthreads();
  mx = red[0];
  #pragma unroll
  for (int j=1;j<8;j++) mx = fmaxf(mx, red[j]);
  __syncthreads();
  float s = 0.f;
  #pragma unroll
  for (int i=0;i<4;i++){ v[i] = expf(v[i]-mx); s += v[i]; }
  #pragma unroll
  for (int o=16;o;o>>=1) s += __shfl_xor_sync(0xffffffffu, s, o);
  if ((tid&31)==0) red[tid>>5] = s;
  __syncthreads();
  s = 0.f;
  #pragma unroll
  for (int j=0;j<8;j++) s += red[j];
  float inv = 1.f/s;
  #pragma unroll
  for (int i=0;i<4;i++){
    int t = tid + i*256;
    if (t < Tt){
      float wv = v[i]*inv;
      g_w[(size_t)hb*Tt + t] = wv;
      if (wout) wout[(size_t)hb*Tt + t] = wv;
    }
  }
}

// ---------------- ctx[h,b,d] = sum_t w[h,b,t]*enc[b,t,d]  (enc read once) ----------
__global__ void ctx_kernel(const float* __restrict__ enc){
  int b = blockIdx.y;
  int d = blockIdx.x*256 + threadIdx.x;
  __shared__ float ws[4][256];
  float a0=0.f,a1=0.f,a2=0.f,a3=0.f;
  for (int t0=0; t0<Tt; t0+=256){
    int n = Tt - t0; if (n > 256) n = 256;
    __syncthreads();
    if ((int)threadIdx.x < n){
      ws[0][threadIdx.x] = g_w[(size_t)(0*Bb+b)*Tt + t0 + threadIdx.x];
      ws[1][threadIdx.x] = g_w[(size_t)(1*Bb+b)*Tt + t0 + threadIdx.x];
      ws[2][threadIdx.x] = g_w[(size_t)(2*Bb+b)*Tt + t0 + threadIdx.x];
      ws[3][threadIdx.x] = g_w[(size_t)(3*Bb+b)*Tt + t0 + threadIdx.x];
    }
    __syncthreads();
    for (int tt=0; tt<n; tt++){
      float ev = enc[(size_t)(b*Tt + t0+tt)*EPROJS + d];
      a0 += ws[0][tt]*ev; a1 += ws[1][tt]*ev; a2 += ws[2][tt]*ev; a3 += ws[3][tt]*ev;
    }
  }
  g_ctx[(size_t)(0*Bb+b)*EPROJS + d] = a0;
  g_ctx[(size_t)(1*Bb+b)*EPROJS + d] = a1;
  g_ctx[(size_t)(2*Bb+b)*EPROJS + d] = a2;
  g_ctx[(size_t)(3*Bb+b)*EPROJS + d] = a3;
}

// ---------------- cv = ctx @ Wv ----------------
__global__ void cv_kernel(const float* __restrict__ Wv){
  int idx = blockIdx.x*blockDim.x + threadIdx.x;
  if (idx >= H*Bb*DVv) return;
  int n = idx % DVv; int hb = idx / DVv;
  int h = hb / Bb;
  const float* cp = g_ctx + (size_t)hb*EPROJS;
  const float* wp = Wv + (size_t)h*EPROJS*DVv + n;
  float s = 0.f;
  #pragma unroll 4
  for (int d=0; d<EPROJS; d++) s += cp[d]*wp[(size_t)d*DVv];
  g_cv[idx] = s;
}

// ---------------- out = concat_h(cv) @ Wo ----------------
__global__ void out_kernel(const float* __restrict__ Wo, float* __restrict__ out){
  int idx = blockIdx.x*blockDim.x + threadIdx.x;
  if (idx >= Bb*EPROJS) return;
  int n = idx % EPROJS; int b = idx / EPROJS;
  float s = 0.f;
  #pragma unroll 4
  for (int k=0; k<H*DVv; k++){
    int h = k >> 9; int e2 = k & 511;
    s += g_cv[(size_t)(h*Bb + b)*DVv + e2] * Wo[(size_t)k*EPROJS + n];
  }
  out[idx] = s;
}

extern "C" void kernel_launch(void* const* d_in, const int* in_sizes, int n_in,
                              void* d_out, int out_size){
  const float* enc   = (const float*)d_in[0];
  // d_in[1] = enc_hs_len (unused: reference applies no masking)
  const float* dec_z = (const float*)d_in[2];
  const float* ap    = (const float*)d_in[3];
  const float* Wq    = (const float*)d_in[4];
  const float* bq    = (const float*)d_in[5];
  const float* Wk    = (const float*)d_in[6];
  const float* Wv    = (const float*)d_in[7];
  const float* gw    = (const float*)d_in[8];
  const float* gb    = (const float*)d_in[9];
  const float* Watt  = (const float*)d_in[10];
  const float* Wo    = (const float*)d_in[11];
  const float* cw0   = (const float*)d_in[12];
  const float* cw1   = (const float*)d_in[13];
  const float* cw2   = (const float*)d_in[14];
  const float* cw3   = (const float*)d_in[15];

  float* out  = (float*)d_out;
  float* wout = (out_size >= (Bb*EPROJS + H*Bb*Tt)) ? out + Bb*EPROJS : nullptr;

  wattp_kernel  <<<(H*CP*DKk + 255)/256, 256>>>(Watt);
  conv_kernel   <<<dim3(8, Bb, H), 128>>>(ap, cw0, cw1, cw2, cw3);
  q_kernel      <<<(H*Bb*DKk + 255)/256, 256>>>(dec_z, Wq, bq);
  energy_kernel <<<dim3(NBLK, MM/64, H), 256>>>(enc, Wk, gw);
  ereduce_kernel<<<(H*MM + 255)/256, 256>>>(gb);
  softmax_kernel<<<H*Bb, 256>>>(wout);
  ctx_kernel    <<<dim3(EPROJS/256, Bb), 256>>>(enc);
  cv_kernel     <<<(H*Bb*DVv + 255)/256, 256>>>(Wv);
  out_kernel    <<<(Bb*EPROJS + 255)/256, 256>>>(Wo, out);
}

// round 3
// speedup vs baseline: 3.5695x; 3.5695x over previous
#include <cuda_runtime.h>
#include <cuda_bf16.h>
#include <math.h>
#include <stdint.h>

#define H 4
#define Bb 32
#define Tt 1000
#define EPROJS 1024
#define DUNITS 1024
#define DKk 512
#define DVv 512
#define CC 100
#define MM (Bb*Tt)        // 32000
#define KTOT 1152         // 1024 (enc/Wk) + 128 (conv/Watt, zero-padded)
#define NBLK 8
#define CTAU 208          // conv K padded to 13*16
#define CSTR 216          // conv smem row stride (bf16)
#define ASTR 40           // energy smem row stride (bf16): 80B = 5 superbanks

// ---------------- scratch ----------------
__device__ __nv_bfloat16 g_encbf[(size_t)MM*EPROJS];       // 65.5MB
__device__ __nv_bfloat16 g_convbf[(size_t)H*MM*128];       // 32.8MB
__device__ __nv_bfloat16 g_Bbf[(size_t)H*DKk*KTOT];        // 4.7MB
__device__ __nv_bfloat16 g_wconvbf[H*128*CTAU];            // padded conv filters
__device__ float g_q[H*Bb*DKk];
__device__ float g_epart[(size_t)NBLK*H*MM];
__device__ float g_e[H*MM];
__device__ float g_w[H*MM];
__device__ float g_ctx[H*Bb*EPROJS];
__device__ float g_cv[H*Bb*DVv];

// ---------------- helpers ----------------
__device__ __forceinline__ float fast_tanh(float x){
  float y; asm("tanh.approx.f32 %0, %1;" : "=f"(y) : "f"(x)); return y;
}
__device__ __forceinline__ uint32_t pack2(float a, float b){
  __nv_bfloat162 t = __floats2bfloat162_rn(a, b);
  return *reinterpret_cast<uint32_t*>(&t);
}
__device__ __forceinline__ void ldsm4(uint32_t& r0, uint32_t& r1, uint32_t& r2, uint32_t& r3, const void* p){
  uint32_t a = (uint32_t)__cvta_generic_to_shared(p);
  asm volatile("ldmatrix.sync.aligned.m8n8.x4.shared.b16 {%0,%1,%2,%3}, [%4];"
               : "=r"(r0), "=r"(r1), "=r"(r2), "=r"(r3) : "r"(a));
}
__device__ __forceinline__ void mma16816(float* c, uint32_t a0, uint32_t a1, uint32_t a2, uint32_t a3,
                                         uint32_t b0, uint32_t b1){
  asm volatile("mma.sync.aligned.m16n8k16.row.col.f32.bf16.bf16.f32 "
               "{%0,%1,%2,%3},{%4,%5,%6,%7},{%8,%9},{%0,%1,%2,%3};"
               : "+f"(c[0]), "+f"(c[1]), "+f"(c[2]), "+f"(c[3])
               : "r"(a0), "r"(a1), "r"(a2), "r"(a3), "r"(b0), "r"(b1));
}

// ---------------- enc -> bf16 ----------------
__global__ void enc2bf_kernel(const float* __restrict__ enc){
  size_t i = ((size_t)blockIdx.x*blockDim.x + threadIdx.x)*4;
  if (i >= (size_t)MM*EPROJS) return;
  float4 v = *(const float4*)(enc + i);
  uint2 o; o.x = pack2(v.x, v.y); o.y = pack2(v.z, v.w);
  *(uint2*)(g_encbf + i) = o;
}

// ---------------- pre-build padded conv filters [H][128][208] bf16 ----------------
__global__ void wconv_kernel(const float* __restrict__ w0, const float* __restrict__ w1,
                             const float* __restrict__ w2, const float* __restrict__ w3){
  int idx = blockIdx.x*blockDim.x + threadIdx.x;
  if (idx >= H*128*CTAU) return;
  int tau = idx % CTAU; int c = (idx/CTAU) % 128; int h = idx/(CTAU*128);
  int F = 25*(h+1), K = 2*F+1;
  const float* wb = (h==0)?w0:(h==1)?w1:(h==2)?w2:w3;
  float v = (c < CC && tau < K) ? wb[c*K + tau] : 0.f;
  g_wconvbf[idx] = __float2bfloat16_rn(v);
}

// ---------------- build B matrix [H][512 n][1152 k] bf16 (Wk^T | Watt^T | 0) -------
__global__ void bbf_kernel(const float* __restrict__ Wk, const float* __restrict__ Watt){
  int idx = blockIdx.x*blockDim.x + threadIdx.x;
  if (idx >= H*DKk*KTOT) return;
  int k = idx % KTOT; int n = (idx/KTOT) % DKk; int h = idx/(KTOT*DKk);
  float v = 0.f;
  if (k < EPROJS)            v = Wk[((size_t)h*EPROJS + k)*DKk + n];
  else if (k < EPROJS + CC)  v = Watt[((size_t)h*CC + (k - EPROJS))*DKk + n];
  g_Bbf[idx] = __float2bfloat16_rn(v);
}

// ---------------- location conv as im2col tensor-core GEMM -> g_convbf -------------
// block: 128 t-rows x 128 c-cols, K = 208 taps (zero-padded weights)
__global__ __launch_bounds__(256) void conv_mma_kernel(const float* __restrict__ ap){
  extern __shared__ char dsm[];
  float* win = (float*)dsm;                              // 336 floats (padded 352)
  __nv_bfloat16* As = (__nv_bfloat16*)(dsm + 1408);      // 128*216 bf16
  __nv_bfloat16* Bs = As + 128*CSTR;

  int h = blockIdx.z, b = blockIdx.y;
  int t0 = blockIdx.x*128;
  int F = 25*(h+1);
  int tid = threadIdx.x;
  const float* arow = ap + (h*Bb + b)*Tt;

  for (int i = tid; i < 336; i += 256){
    int tt = t0 - F + i;
    win[i] = (tt >= 0 && tt < Tt) ? arow[tt] : 0.f;
  }
  const __nv_bfloat16* wsrc = g_wconvbf + h*128*CTAU;
  for (int ch = tid; ch < 128*26; ch += 256){
    int c = ch/26, t8 = (ch%26)*8;
    *(uint4*)&Bs[c*CSTR + t8] = *(const uint4*)(wsrc + c*CTAU + t8);
  }
  __syncthreads();
  for (int ch = tid; ch < 128*26; ch += 256){
    int r = ch/26, t8 = (ch%26)*8;
    uint4 v;
    v.x = pack2(win[r+t8+0], win[r+t8+1]);
    v.y = pack2(win[r+t8+2], win[r+t8+3]);
    v.z = pack2(win[r+t8+4], win[r+t8+5]);
    v.w = pack2(win[r+t8+6], win[r+t8+7]);
    *(uint4*)&As[r*CSTR + t8] = v;
  }
  __syncthreads();

  int warp = tid>>5, lane = tid&31;
  int wm = warp>>1, wn = warp&1;
  float acc[2][8][4];
  #pragma unroll
  for (int i=0;i<2;i++) for (int j=0;j<8;j++) for (int k=0;k<4;k++) acc[i][j][k]=0.f;

  #pragma unroll
  for (int k16 = 0; k16 < 13; k16++){
    uint32_t af[2][4];
    #pragma unroll
    for (int mt=0;mt<2;mt++)
      ldsm4(af[mt][0],af[mt][1],af[mt][2],af[mt][3],
        &As[(wm*32 + mt*16 + ((lane>>3)&1)*8 + (lane&7))*CSTR + k16*16 + ((lane>>4)&1)*8]);
    uint32_t bfr[8][2];
    #pragma unroll
    for (int j=0;j<4;j++){
      uint32_t r0,r1,r2,r3;
      ldsm4(r0,r1,r2,r3,
        &Bs[(wn*64 + (2*j + ((lane>>4)&1))*8 + (lane&7))*CSTR + k16*16 + ((lane>>3)&1)*8]);
      bfr[2*j][0]=r0; bfr[2*j][1]=r1; bfr[2*j+1][0]=r2; bfr[2*j+1][1]=r3;
    }
    #pragma unroll
    for (int mt=0;mt<2;mt++)
      #pragma unroll
      for (int nt=0;nt<8;nt++)
        mma16816(acc[mt][nt], af[mt][0],af[mt][1],af[mt][2],af[mt][3], bfr[nt][0], bfr[nt][1]);
  }

  int g = lane>>2, tg = lane&3;
  __nv_bfloat16* outp = g_convbf + ((size_t)h*MM + (size_t)b*Tt)*128;
  #pragma unroll
  for (int mt=0;mt<2;mt++)
    #pragma unroll
    for (int rh=0;rh<2;rh++){
      int trow = t0 + wm*32 + mt*16 + g + rh*8;
      if (trow < Tt){
        #pragma unroll
        for (int nt=0;nt<8;nt++){
          int col = wn*64 + nt*8 + tg*2;
          uint32_t pv = pack2(acc[mt][nt][rh*2+0], acc[mt][nt][rh*2+1]);
          *(uint32_t*)&outp[(size_t)trow*128 + col] = pv;
        }
      }
    }
}

// ---------------- q = dec_z @ Wq + bq (fp32) ----------------
__global__ void q_kernel(const float* __restrict__ dec_z, const float* __restrict__ Wq,
                         const float* __restrict__ bq){
  int idx = blockIdx.x*blockDim.x + threadIdx.x;
  if (idx >= H*Bb*DKk) return;
  int n = idx % DKk; int b = (idx / DKk) % Bb; int h = idx / (DKk*Bb);
  const float* z  = dec_z + b*DUNITS;
  const float* wp = Wq + (size_t)h*DUNITS*DKk + n;
  float s = bq[h*DKk + n];
  #pragma unroll 4
  for (int d = 0; d < DUNITS; d++) s += z[d]*wp[(size_t)d*DKk];
  g_q[idx] = s;
}

// ---------------- fused energy GEMM (tensor cores) ----------------
// C = A[128 m x 1152 k] * B[1152 k x 128 n]; epilogue: +q, tanh, * g_w, row-reduce
__global__ __launch_bounds__(256) void energy_mma_kernel(const float* __restrict__ gw){
  __shared__ __align__(16) __nv_bfloat16 As[2][128*ASTR];
  __shared__ __align__(16) __nv_bfloat16 Bs[2][128*ASTR];
  int h = blockIdx.z;
  int m0 = blockIdx.y*128, n0 = blockIdx.x*128;
  int tid = threadIdx.x, warp = tid>>5, lane = tid&31;
  int wm = warp>>1, wn = warp&1;
  int lrow = tid>>1, lhalf = tid&1;

  const __nv_bfloat16* Arow_enc  = g_encbf + (size_t)(m0+lrow)*EPROJS;
  const __nv_bfloat16* Arow_conv = g_convbf + ((size_t)h*MM + m0 + lrow)*128;
  const __nv_bfloat16* Brow      = g_Bbf + ((size_t)h*DKk + n0 + lrow)*KTOT;

  float acc[2][8][4];
  #pragma unroll
  for (int i=0;i<2;i++) for (int j=0;j<8;j++) for (int k=0;k<4;k++) acc[i][j][k]=0.f;

  uint4 av0, av1, bv0, bv1;
  {
    const uint4* ap4 = (const uint4*)(Arow_enc + lhalf*16);
    av0 = ap4[0]; av1 = ap4[1];
    const uint4* bp4 = (const uint4*)(Brow + lhalf*16);
    bv0 = bp4[0]; bv1 = bp4[1];
  }
  int p = 0;
  *(uint4*)&As[0][lrow*ASTR + lhalf*16]     = av0;
  *(uint4*)&As[0][lrow*ASTR + lhalf*16 + 8] = av1;
  *(uint4*)&Bs[0][lrow*ASTR + lhalf*16]     = bv0;
  *(uint4*)&Bs[0][lrow*ASTR + lhalf*16 + 8] = bv1;
  __syncthreads();

  for (int kc = 0; kc < 36; kc++){
    int nk = kc + 1;
    if (nk < 36){
      const __nv_bfloat16* asrc = (nk < 32) ? (Arow_enc + nk*32 + lhalf*16)
                                            : (Arow_conv + (nk-32)*32 + lhalf*16);
      const uint4* ap4 = (const uint4*)asrc; av0 = ap4[0]; av1 = ap4[1];
      const uint4* bp4 = (const uint4*)(Brow + nk*32 + lhalf*16); bv0 = bp4[0]; bv1 = bp4[1];
    }
    const __nv_bfloat16* Ab = As[p];
    const __nv_bfloat16* Bp = Bs[p];
    #pragma unroll
    for (int kk=0;kk<2;kk++){
      uint32_t af[2][4];
      #pragma unroll
      for (int mt=0;mt<2;mt++)
        ldsm4(af[mt][0],af[mt][1],af[mt][2],af[mt][3],
          &Ab[(wm*32 + mt*16 + ((lane>>3)&1)*8 + (lane&7))*ASTR + kk*16 + ((lane>>4)&1)*8]);
      uint32_t bfr[8][2];
      #pragma unroll
      for (int j=0;j<4;j++){
        uint32_t r0,r1,r2,r3;
        ldsm4(r0,r1,r2,r3,
          &Bp[(wn*64 + (2*j + ((lane>>4)&1))*8 + (lane&7))*ASTR + kk*16 + ((lane>>3)&1)*8]);
        bfr[2*j][0]=r0; bfr[2*j][1]=r1; bfr[2*j+1][0]=r2; bfr[2*j+1][1]=r3;
      }
      #pragma unroll
      for (int mt=0;mt<2;mt++)
        #pragma unroll
        for (int nt=0;nt<8;nt++)
          mma16816(acc[mt][nt], af[mt][0],af[mt][1],af[mt][2],af[mt][3], bfr[nt][0], bfr[nt][1]);
    }
    if (nk < 36){
      int q = p ^ 1;
      *(uint4*)&As[q][lrow*ASTR + lhalf*16]     = av0;
      *(uint4*)&As[q][lrow*ASTR + lhalf*16 + 8] = av1;
      *(uint4*)&Bs[q][lrow*ASTR + lhalf*16]     = bv0;
      *(uint4*)&Bs[q][lrow*ASTR + lhalf*16 + 8] = bv1;
      __syncthreads();
      p = q;
    }
  }

  // epilogue
  int g = lane>>2, tg = lane&3;
  const float* gwp = gw + h*DKk + n0 + wn*64;
  float gwv[8][2];
  #pragma unroll
  for (int nt=0;nt<8;nt++){
    gwv[nt][0] = gwp[nt*8 + tg*2];
    gwv[nt][1] = gwp[nt*8 + tg*2 + 1];
  }
  #pragma unroll
  for (int mt=0;mt<2;mt++)
    #pragma unroll
    for (int rh=0;rh<2;rh++){
      int row = m0 + wm*32 + mt*16 + g + rh*8;
      int bb = row / Tt;
      const float* qp = g_q + (size_t)(h*Bb + bb)*DKk + n0 + wn*64;
      float psum = 0.f;
      #pragma unroll
      for (int nt=0;nt<8;nt++){
        int cb = nt*8 + tg*2;
        psum += fast_tanh(acc[mt][nt][rh*2+0] + qp[cb])   * gwv[nt][0];
        psum += fast_tanh(acc[mt][nt][rh*2+1] + qp[cb+1]) * gwv[nt][1];
      }
      psum += __shfl_xor_sync(0xffffffffu, psum, 1);
      psum += __shfl_xor_sync(0xffffffffu, psum, 2);
      if (tg == 0)
        g_epart[(size_t)(blockIdx.x*2 + wn)*(H*MM) + (size_t)h*MM + row] = psum;
    }
}

// ---------------- deterministic reduction ----------------
__global__ void ereduce_kernel(const float* __restrict__ gb){
  int idx = blockIdx.x*blockDim.x + threadIdx.x;
  if (idx >= H*MM) return;
  int h = idx / MM;
  float s = gb[h];
  #pragma unroll
  for (int j=0;j<NBLK;j++) s += g_epart[(size_t)j*(H*MM) + idx];
  g_e[idx] = s;
}

// ---------------- softmax over T per (h,b) ----------------
__global__ void softmax_kernel(float* __restrict__ wout){
  __shared__ float red[8];
  int hb = blockIdx.x;
  const float scale = 0.04419417382415922f;  // 1/sqrt(512)
  const float* ep = g_e + (size_t)hb*Tt;
  int tid = threadIdx.x;
  float v[4];
  float mx = -1e30f;
  #pragma unroll
  for (int i=0;i<4;i++){
    int t = tid + i*256;
    v[i] = (t < Tt) ? ep[t]*scale : -1e30f;
    mx = fmaxf(mx, v[i]);
  }
  #pragma unroll
  for (int o=16;o;o>>=1) mx = fmaxf(mx, __shfl_xor_sync(0xffffffffu, mx, o));
  if ((tid&31)==0) red[tid>>5] = mx;
  __syncthreads();
  mx = red[0];
  #pragma unroll
  for (int j=1;j<8;j++) mx = fmaxf(mx, red[j]);
  __syncthreads();
  float s = 0.f;
  #pragma unroll
  for (int i=0;i<4;i++){ v[i] = expf(v[i]-mx); s += v[i]; }
  #pragma unroll
  for (int o=16;o;o>>=1) s += __shfl_xor_sync(0xffffffffu, s, o);
  if ((tid&31)==0) red[tid>>5] = s;
  __syncthreads();
  s = 0.f;
  #pragma unroll
  for (int j=0;j<8;j++) s += red[j];
  float inv = 1.f/s;
  #pragma unroll
  for (int i=0;i<4;i++){
    int t = tid + i*256;
    if (t < Tt){
      float wv = v[i]*inv;
      g_w[(size_t)hb*Tt + t] = wv;
      if (wout) wout[(size_t)hb*Tt + t] = wv;
    }
  }
}

// ---------------- ctx[h,b,d] = sum_t w[h,b,t]*enc[b,t,d] (fp32) ----------------
__global__ void ctx_kernel(const float* __restrict__ enc){
  int b = blockIdx.y;
  int d = blockIdx.x*256 + threadIdx.x;
  __shared__ float ws[4][256];
  float a0=0.f,a1=0.f,a2=0.f,a3=0.f;
  for (int t0=0; t0<Tt; t0+=256){
    int n = Tt - t0; if (n > 256) n = 256;
    __syncthreads();
    if ((int)threadIdx.x < n){
      ws[0][threadIdx.x] = g_w[(size_t)(0*Bb+b)*Tt + t0 + threadIdx.x];
      ws[1][threadIdx.x] = g_w[(size_t)(1*Bb+b)*Tt + t0 + threadIdx.x];
      ws[2][threadIdx.x] = g_w[(size_t)(2*Bb+b)*Tt + t0 + threadIdx.x];
      ws[3][threadIdx.x] = g_w[(size_t)(3*Bb+b)*Tt + t0 + threadIdx.x];
    }
    __syncthreads();
    for (int tt=0; tt<n; tt++){
      float ev = enc[(size_t)(b*Tt + t0+tt)*EPROJS + d];
      a0 += ws[0][tt]*ev; a1 += ws[1][tt]*ev; a2 += ws[2][tt]*ev; a3 += ws[3][tt]*ev;
    }
  }
  g_ctx[(size_t)(0*Bb+b)*EPROJS + d] = a0;
  g_ctx[(size_t)(1*Bb+b)*EPROJS + d] = a1;
  g_ctx[(size_t)(2*Bb+b)*EPROJS + d] = a2;
  g_ctx[(size_t)(3*Bb+b)*EPROJS + d] = a3;
}

// ---------------- cv = ctx @ Wv ----------------
__global__ void cv_kernel(const float* __restrict__ Wv){
  int idx = blockIdx.x*blockDim.x + threadIdx.x;
  if (idx >= H*Bb*DVv) return;
  int n = idx % DVv; int hb = idx / DVv;
  int h = hb / Bb;
  const float* cp = g_ctx + (size_t)hb*EPROJS;
  const float* wp = Wv + (size_t)h*EPROJS*DVv + n;
  float s = 0.f;
  #pragma unroll 4
  for (int d=0; d<EPROJS; d++) s += cp[d]*wp[(size_t)d*DVv];
  g_cv[idx] = s;
}

// ---------------- out = concat_h(cv) @ Wo ----------------
__global__ void out_kernel(const float* __restrict__ Wo, float* __restrict__ out){
  int idx = blockIdx.x*blockDim.x + threadIdx.x;
  if (idx >= Bb*EPROJS) return;
  int n = idx % EPROJS; int b = idx / EPROJS;
  float s = 0.f;
  #pragma unroll 4
  for (int k=0; k<H*DVv; k++){
    int h = k >> 9; int e2 = k & 511;
    s += g_cv[(size_t)(h*Bb + b)*DVv + e2] * Wo[(size_t)k*EPROJS + n];
  }
  out[idx] = s;
}

extern "C" void kernel_launch(void* const* d_in, const int* in_sizes, int n_in,
                              void* d_out, int out_size){
  const float* enc   = (const float*)d_in[0];
  // d_in[1] = enc_hs_len (unused: reference applies no masking)
  const float* dec_z = (const float*)d_in[2];
  const float* ap    = (const float*)d_in[3];
  const float* Wq    = (const float*)d_in[4];
  const float* bq    = (const float*)d_in[5];
  const float* Wk    = (const float*)d_in[6];
  const float* Wv    = (const float*)d_in[7];
  const float* gw    = (const float*)d_in[8];
  const float* gb    = (const float*)d_in[9];
  const float* Watt  = (const float*)d_in[10];
  const float* Wo    = (const float*)d_in[11];
  const float* cw0   = (const float*)d_in[12];
  const float* cw1   = (const float*)d_in[13];
  const float* cw2   = (const float*)d_in[14];
  const float* cw3   = (const float*)d_in[15];

  float* out  = (float*)d_out;
  float* wout = (out_size >= (Bb*EPROJS + H*Bb*Tt)) ? out + Bb*EPROJS : nullptr;

  const int CONV_SMEM = 1408 + 2*128*CSTR*2;  // win + As + Bs = 112000B
  cudaFuncSetAttribute(conv_mma_kernel, cudaFuncAttributeMaxDynamicSharedMemorySize, CONV_SMEM);

  enc2bf_kernel  <<<(MM*EPROJS/4 + 255)/256, 256>>>(enc);
  wconv_kernel   <<<(H*128*CTAU + 255)/256, 256>>>(cw0, cw1, cw2, cw3);
  bbf_kernel     <<<(H*DKk*KTOT + 255)/256, 256>>>(Wk, Watt);
  conv_mma_kernel<<<dim3(8, Bb, H), 256, CONV_SMEM>>>(ap);
  q_kernel       <<<(H*Bb*DKk + 255)/256, 256>>>(dec_z, Wq, bq);
  energy_mma_kernel<<<dim3(4, 250, H), 256>>>(gw);
  ereduce_kernel <<<(H*MM + 255)/256, 256>>>(gb);
  softmax_kernel <<<H*Bb, 256>>>(wout);
  ctx_kernel     <<<dim3(EPROJS/256, Bb), 256>>>(enc);
  cv_kernel      <<<(H*Bb*DVv + 255)/256, 256>>>(Wv);
  out_kernel     <<<(Bb*EPROJS + 255)/256, 256>>>(Wo, out);
}

// round 6
// speedup vs baseline: 4.0428x; 1.1326x over previous
#include <cuda_runtime.h>
#include <cuda_bf16.h>
#include <math.h>
#include <stdint.h>

#define H 4
#define Bb 32
#define Tt 1000
#define EPROJS 1024
#define DUNITS 1024
#define DKk 512
#define DVv 512
#define CC 100
#define MM (Bb*Tt)        // 32000
#define KTOT 1152         // 1024 (enc/Wk) + 128 (conv/Watt, zero-padded)
#define NBLK 8
#define CTAU 208          // conv K padded to 13*16
#define CSTR 216          // conv smem row stride (bf16)
#define ESTR 40           // energy smem row stride (bf16): 80B = 5 superbanks
#define STGB (2*128*ESTR*2)   // bytes per pipeline stage (A tile + B tile) = 20480
#define NCHUNK 36             // 1152 / 32

// ---------------- scratch ----------------
__device__ __align__(256) __nv_bfloat16 g_encbf[(size_t)MM*EPROJS];
__device__ __align__(256) __nv_bfloat16 g_convbf[(size_t)H*MM*128];
__device__ __align__(256) __nv_bfloat16 g_Bbf[(size_t)H*DKk*KTOT];
__device__ __align__(256) __nv_bfloat16 g_wconvbf[H*128*CTAU];
__device__ float g_q[H*Bb*DKk];
__device__ float g_epart[(size_t)NBLK*H*MM];
__device__ float g_e[H*MM];
__device__ float g_w[H*MM];
__device__ float g_ctx[H*Bb*EPROJS];
__device__ float g_cv[H*Bb*DVv];

// ---------------- helpers ----------------
__device__ __forceinline__ uint32_t smem_u32(const void* p){
  uint32_t a;
  asm("{ .reg .u64 t; cvta.to.shared.u64 t, %1; cvt.u32.u64 %0, t; }" : "=r"(a) : "l"(p));
  return a;
}
__device__ __forceinline__ void cp_async16(uint32_t dst, const void* src){
  asm volatile("cp.async.cg.shared.global [%0], [%1], 16;" :: "r"(dst), "l"(src) : "memory");
}
#define CP_COMMIT() asm volatile("cp.async.commit_group;" ::: "memory")
#define CP_WAIT3()  asm volatile("cp.async.wait_group 3;" ::: "memory")

__device__ __forceinline__ float fast_tanh(float x){
  float y; asm("tanh.approx.f32 %0, %1;" : "=f"(y) : "f"(x)); return y;
}
__device__ __forceinline__ uint32_t pack2(float a, float b){
  __nv_bfloat162 t = __floats2bfloat162_rn(a, b);
  return *reinterpret_cast<uint32_t*>(&t);
}
__device__ __forceinline__ void ldsm4(uint32_t& r0, uint32_t& r1, uint32_t& r2, uint32_t& r3, const void* p){
  uint32_t a = (uint32_t)__cvta_generic_to_shared(p);
  asm volatile("ldmatrix.sync.aligned.m8n8.x4.shared.b16 {%0,%1,%2,%3}, [%4];"
               : "=r"(r0), "=r"(r1), "=r"(r2), "=r"(r3) : "r"(a));
}
__device__ __forceinline__ void mma16816(float* c, uint32_t a0, uint32_t a1, uint32_t a2, uint32_t a3,
                                         uint32_t b0, uint32_t b1){
  asm volatile("mma.sync.aligned.m16n8k16.row.col.f32.bf16.bf16.f32 "
               "{%0,%1,%2,%3},{%4,%5,%6,%7},{%8,%9},{%0,%1,%2,%3};"
               : "+f"(c[0]), "+f"(c[1]), "+f"(c[2]), "+f"(c[3])
               : "r"(a0), "r"(a1), "r"(a2), "r"(a3), "r"(b0), "r"(b1));
}

// ---------------- enc -> bf16 ----------------
__global__ void enc2bf_kernel(const float* __restrict__ enc){
  size_t i = ((size_t)blockIdx.x*blockDim.x + threadIdx.x)*4;
  if (i >= (size_t)MM*EPROJS) return;
  float4 v = *(const float4*)(enc + i);
  uint2 o; o.x = pack2(v.x, v.y); o.y = pack2(v.z, v.w);
  *(uint2*)(g_encbf + i) = o;
}

// ---------------- padded conv filters ----------------
__global__ void wconv_kernel(const float* __restrict__ w0, const float* __restrict__ w1,
                             const float* __restrict__ w2, const float* __restrict__ w3){
  int idx = blockIdx.x*blockDim.x + threadIdx.x;
  if (idx >= H*128*CTAU) return;
  int tau = idx % CTAU; int c = (idx/CTAU) % 128; int h = idx/(CTAU*128);
  int F = 25*(h+1), K = 2*F+1;
  const float* wb = (h==0)?w0:(h==1)?w1:(h==2)?w2:w3;
  float v = (c < CC && tau < K) ? wb[c*K + tau] : 0.f;
  g_wconvbf[idx] = __float2bfloat16_rn(v);
}

// ---------------- B matrix [H][512 n][1152 k] bf16 (Wk^T | Watt^T | 0) -------------
__global__ void bbf_kernel(const float* __restrict__ Wk, const float* __restrict__ Watt){
  int idx = blockIdx.x*blockDim.x + threadIdx.x;
  if (idx >= H*DKk*KTOT) return;
  int k = idx % KTOT; int n = (idx/KTOT) % DKk; int h = idx/(KTOT*DKk);
  float v = 0.f;
  if (k < EPROJS)            v = Wk[((size_t)h*EPROJS + k)*DKk + n];
  else if (k < EPROJS + CC)  v = Watt[((size_t)h*CC + (k - EPROJS))*DKk + n];
  g_Bbf[idx] = __float2bfloat16_rn(v);
}

// ---------------- location conv as im2col mma GEMM -> g_convbf ----------------
__global__ __launch_bounds__(256) void conv_mma_kernel(const float* __restrict__ ap){
  extern __shared__ char dsm[];
  float* win = (float*)dsm;
  __nv_bfloat16* As = (__nv_bfloat16*)(dsm + 1408);
  __nv_bfloat16* Bs = As + 128*CSTR;

  int h = blockIdx.z, b = blockIdx.y;
  int t0 = blockIdx.x*128;
  int F = 25*(h+1);
  int tid = threadIdx.x;
  const float* arow = ap + (h*Bb + b)*Tt;

  for (int i = tid; i < 336; i += 256){
    int tt = t0 - F + i;
    win[i] = (tt >= 0 && tt < Tt) ? arow[tt] : 0.f;
  }
  const __nv_bfloat16* wsrc = g_wconvbf + h*128*CTAU;
  for (int ch = tid; ch < 128*26; ch += 256){
    int c = ch/26, t8 = (ch%26)*8;
    *(uint4*)&Bs[c*CSTR + t8] = *(const uint4*)(wsrc + c*CTAU + t8);
  }
  __syncthreads();
  for (int ch = tid; ch < 128*26; ch += 256){
    int r = ch/26, t8 = (ch%26)*8;
    uint4 v;
    v.x = pack2(win[r+t8+0], win[r+t8+1]);
    v.y = pack2(win[r+t8+2], win[r+t8+3]);
    v.z = pack2(win[r+t8+4], win[r+t8+5]);
    v.w = pack2(win[r+t8+6], win[r+t8+7]);
    *(uint4*)&As[r*CSTR + t8] = v;
  }
  __syncthreads();

  int warp = tid>>5, lane = tid&31;
  int wm = warp>>1, wn = warp&1;
  float acc[2][8][4];
  #pragma unroll
  for (int i=0;i<2;i++) for (int j=0;j<8;j++) for (int k=0;k<4;k++) acc[i][j][k]=0.f;

  #pragma unroll
  for (int k16 = 0; k16 < 13; k16++){
    uint32_t af[2][4];
    #pragma unroll
    for (int mt=0;mt<2;mt++)
      ldsm4(af[mt][0],af[mt][1],af[mt][2],af[mt][3],
        &As[(wm*32 + mt*16 + ((lane>>3)&1)*8 + (lane&7))*CSTR + k16*16 + ((lane>>4)&1)*8]);
    uint32_t bfr[8][2];
    #pragma unroll
    for (int j=0;j<4;j++){
      uint32_t r0,r1,r2,r3;
      ldsm4(r0,r1,r2,r3,
        &Bs[(wn*64 + (2*j + ((lane>>4)&1))*8 + (lane&7))*CSTR + k16*16 + ((lane>>3)&1)*8]);
      bfr[2*j][0]=r0; bfr[2*j][1]=r1; bfr[2*j+1][0]=r2; bfr[2*j+1][1]=r3;
    }
    #pragma unroll
    for (int mt=0;mt<2;mt++)
      #pragma unroll
      for (int nt=0;nt<8;nt++)
        mma16816(acc[mt][nt], af[mt][0],af[mt][1],af[mt][2],af[mt][3], bfr[nt][0], bfr[nt][1]);
  }

  int g = lane>>2, tg = lane&3;
  __nv_bfloat16* outp = g_convbf + ((size_t)h*MM + (size_t)b*Tt)*128;
  #pragma unroll
  for (int mt=0;mt<2;mt++)
    #pragma unroll
    for (int rh=0;rh<2;rh++){
      int trow = t0 + wm*32 + mt*16 + g + rh*8;
      if (trow < Tt){
        #pragma unroll
        for (int nt=0;nt<8;nt++){
          int col = wn*64 + nt*8 + tg*2;
          uint32_t pv = pack2(acc[mt][nt][rh*2+0], acc[mt][nt][rh*2+1]);
          *(uint32_t*)&outp[(size_t)trow*128 + col] = pv;
        }
      }
    }
}

// ---------------- q = dec_z @ Wq + bq ----------------
__global__ void q_kernel(const float* __restrict__ dec_z, const float* __restrict__ Wq,
                         const float* __restrict__ bq){
  int idx = blockIdx.x*blockDim.x + threadIdx.x;
  if (idx >= H*Bb*DKk) return;
  int n = idx % DKk; int b = (idx / DKk) % Bb; int h = idx / (DKk*Bb);
  const float* z  = dec_z + b*DUNITS;
  const float* wp = Wq + (size_t)h*DUNITS*DKk + n;
  float s = bq[h*DKk + n];
  #pragma unroll 4
  for (int d = 0; d < DUNITS; d++) s += z[d]*wp[(size_t)d*DKk];
  g_q[idx] = s;
}

// ---------------- fused energy GEMM: 4 warps x (64x64), cp.async 4-stage ----------
// grid (4, 250, 4): CTA = 128 m-rows x 128 n-cols, K = 1152 in 36 chunks of 32
__global__ __launch_bounds__(128) void energy_mma_kernel(const float* __restrict__ gw){
  extern __shared__ __align__(16) __nv_bfloat16 es[];
  uint32_t smem_base = smem_u32(es);
  int h = blockIdx.z;
  int m0 = blockIdx.y*128, n0 = blockIdx.x*128;
  int tid = threadIdx.x, warp = tid>>5, lane = tid&31;
  int wm = warp>>1, wn = warp&1;

  const __nv_bfloat16* encp  = g_encbf + (size_t)m0*EPROJS;
  const __nv_bfloat16* convp = g_convbf + ((size_t)h*MM + m0)*128;
  const __nv_bfloat16* Bp    = g_Bbf + ((size_t)h*DKk + n0)*KTOT;

  float acc[4][8][4];
  #pragma unroll
  for (int i=0;i<4;i++) for (int j=0;j<8;j++) for (int k=0;k<4;k++) acc[i][j][k]=0.f;

  auto issue_chunk = [&](int c){
    uint32_t sbase = smem_base + (uint32_t)(c & 3)*STGB;
    #pragma unroll
    for (int i=0;i<4;i++){
      int idx = tid + i*128;
      int row = idx>>2, q = idx&3;
      const __nv_bfloat16* src = (c < 32) ? (encp + (size_t)row*EPROJS + c*32 + q*8)
                                          : (convp + (size_t)row*128 + (c-32)*32 + q*8);
      cp_async16(sbase + (uint32_t)(row*ESTR + q*8)*2, src);
    }
    #pragma unroll
    for (int i=0;i<4;i++){
      int idx = tid + i*128;
      int row = idx>>2, q = idx&3;
      cp_async16(sbase + (uint32_t)(128*ESTR + row*ESTR + q*8)*2,
                 Bp + (size_t)row*KTOT + c*32 + q*8);
    }
  };

  issue_chunk(0); CP_COMMIT();
  issue_chunk(1); CP_COMMIT();
  issue_chunk(2); CP_COMMIT();

  for (int c = 0; c < NCHUNK; c++){
    __syncthreads();                 // all warps done with chunk c-1 (stage (c+3)&3)
    if (c + 3 < NCHUNK) issue_chunk(c + 3);
    CP_COMMIT();
    CP_WAIT3();                      // chunk c resident
    __syncthreads();

    const __nv_bfloat16* As = es + (c & 3)*(2*128*ESTR);
    const __nv_bfloat16* Bs = As + 128*ESTR;
    #pragma unroll
    for (int kk = 0; kk < 2; kk++){
      uint32_t af[4][4];
      #pragma unroll
      for (int mt=0;mt<4;mt++)
        ldsm4(af[mt][0],af[mt][1],af[mt][2],af[mt][3],
          &As[(wm*64 + mt*16 + ((lane>>3)&1)*8 + (lane&7))*ESTR + kk*16 + ((lane>>4)&1)*8]);
      uint32_t bfr[8][2];
      #pragma unroll
      for (int j=0;j<4;j++){
        uint32_t r0,r1,r2,r3;
        ldsm4(r0,r1,r2,r3,
          &Bs[(wn*64 + (2*j + ((lane>>4)&1))*8 + (lane&7))*ESTR + kk*16 + ((lane>>3)&1)*8]);
        bfr[2*j][0]=r0; bfr[2*j][1]=r1; bfr[2*j+1][0]=r2; bfr[2*j+1][1]=r3;
      }
      #pragma unroll
      for (int mt=0;mt<4;mt++)
        #pragma unroll
        for (int nt=0;nt<8;nt++)
          mma16816(acc[mt][nt], af[mt][0],af[mt][1],af[mt][2],af[mt][3], bfr[nt][0], bfr[nt][1]);
    }
  }

  // epilogue: +q, tanh, * g_w, reduce over this warp's 64 cols
  int g = lane>>2, tg = lane&3;
  const float* gwp = gw + h*DKk + n0 + wn*64;
  float gwv[8][2];
  #pragma unroll
  for (int nt=0;nt<8;nt++){
    gwv[nt][0] = gwp[nt*8 + tg*2];
    gwv[nt][1] = gwp[nt*8 + tg*2 + 1];
  }
  #pragma unroll
  for (int mt=0;mt<4;mt++)
    #pragma unroll
    for (int rh=0;rh<2;rh++){
      int row = m0 + wm*64 + mt*16 + g + rh*8;
      int bb = row / Tt;
      const float* qp = g_q + (size_t)(h*Bb + bb)*DKk + n0 + wn*64;
      float psum = 0.f;
      #pragma unroll
      for (int nt=0;nt<8;nt++){
        int cb = nt*8 + tg*2;
        psum += fast_tanh(acc[mt][nt][rh*2+0] + qp[cb])   * gwv[nt][0];
        psum += fast_tanh(acc[mt][nt][rh*2+1] + qp[cb+1]) * gwv[nt][1];
      }
      psum += __shfl_xor_sync(0xffffffffu, psum, 1);
      psum += __shfl_xor_sync(0xffffffffu, psum, 2);
      if (tg == 0)
        g_epart[(size_t)(blockIdx.x*2 + wn)*(H*MM) + (size_t)h*MM + row] = psum;
    }
}

// ---------------- deterministic reduction ----------------
__global__ void ereduce_kernel(const float* __restrict__ gb){
  int idx = blockIdx.x*blockDim.x + threadIdx.x;
  if (idx >= H*MM) return;
  int h = idx / MM;
  float s = gb[h];
  #pragma unroll
  for (int j=0;j<NBLK;j++) s += g_epart[(size_t)j*(H*MM) + idx];
  g_e[idx] = s;
}

// ---------------- softmax over T per (h,b) ----------------
__global__ void softmax_kernel(float* __restrict__ wout){
  __shared__ float red[8];
  int hb = blockIdx.x;
  const float scale = 0.04419417382415922f;  // 1/sqrt(512)
  const float* ep = g_e + (size_t)hb*Tt;
  int tid = threadIdx.x;
  float v[4];
  float mx = -1e30f;
  #pragma unroll
  for (int i=0;i<4;i++){
    int t = tid + i*256;
    v[i] = (t < Tt) ? ep[t]*scale : -1e30f;
    mx = fmaxf(mx, v[i]);
  }
  #pragma unroll
  for (int o=16;o;o>>=1) mx = fmaxf(mx, __shfl_xor_sync(0xffffffffu, mx, o));
  if ((tid&31)==0) red[tid>>5] = mx;
  __syncthreads();
  mx = red[0];
  #pragma unroll
  for (int j=1;j<8;j++) mx = fmaxf(mx, red[j]);
  __syncthreads();
  float s = 0.f;
  #pragma unroll
  for (int i=0;i<4;i++){ v[i] = expf(v[i]-mx); s += v[i]; }
  #pragma unroll
  for (int o=16;o;o>>=1) s += __shfl_xor_sync(0xffffffffu, s, o);
  if ((tid&31)==0) red[tid>>5] = s;
  __syncthreads();
  s = 0.f;
  #pragma unroll
  for (int j=0;j<8;j++) s += red[j];
  float inv = 1.f/s;
  #pragma unroll
  for (int i=0;i<4;i++){
    int t = tid + i*256;
    if (t < Tt){
      float wv = v[i]*inv;
      g_w[(size_t)hb*Tt + t] = wv;
      if (wout) wout[(size_t)hb*Tt + t] = wv;
    }
  }
}

// ---------------- ctx[h,b,d] = sum_t w[h,b,t]*enc[b,t,d] (fp32) ----------------
__global__ void ctx_kernel(const float* __restrict__ enc){
  int b = blockIdx.y;
  int d = blockIdx.x*256 + threadIdx.x;
  __shared__ float ws[4][256];
  float a0=0.f,a1=0.f,a2=0.f,a3=0.f;
  for (int t0=0; t0<Tt; t0+=256){
    int n = Tt - t0; if (n > 256) n = 256;
    __syncthreads();
    if ((int)threadIdx.x < n){
      ws[0][threadIdx.x] = g_w[(size_t)(0*Bb+b)*Tt + t0 + threadIdx.x];
      ws[1][threadIdx.x] = g_w[(size_t)(1*Bb+b)*Tt + t0 + threadIdx.x];
      ws[2][threadIdx.x] = g_w[(size_t)(2*Bb+b)*Tt + t0 + threadIdx.x];
      ws[3][threadIdx.x] = g_w[(size_t)(3*Bb+b)*Tt + t0 + threadIdx.x];
    }
    __syncthreads();
    for (int tt=0; tt<n; tt++){
      float ev = enc[(size_t)(b*Tt + t0+tt)*EPROJS + d];
      a0 += ws[0][tt]*ev; a1 += ws[1][tt]*ev; a2 += ws[2][tt]*ev; a3 += ws[3][tt]*ev;
    }
  }
  g_ctx[(size_t)(0*Bb+b)*EPROJS + d] = a0;
  g_ctx[(size_t)(1*Bb+b)*EPROJS + d] = a1;
  g_ctx[(size_t)(2*Bb+b)*EPROJS + d] = a2;
  g_ctx[(size_t)(3*Bb+b)*EPROJS + d] = a3;
}

// ---------------- cv = ctx @ Wv ----------------
__global__ void cv_kernel(const float* __restrict__ Wv){
  int idx = blockIdx.x*blockDim.x + threadIdx.x;
  if (idx >= H*Bb*DVv) return;
  int n = idx % DVv; int hb = idx / DVv;
  int h = hb / Bb;
  const float* cp = g_ctx + (size_t)hb*EPROJS;
  const float* wp = Wv + (size_t)h*EPROJS*DVv + n;
  float s = 0.f;
  #pragma unroll 4
  for (int d=0; d<EPROJS; d++) s += cp[d]*wp[(size_t)d*DVv];
  g_cv[idx] = s;
}

// ---------------- out = concat_h(cv) @ Wo ----------------
__global__ void out_kernel(const float* __restrict__ Wo, float* __restrict__ out){
  int idx = blockIdx.x*blockDim.x + threadIdx.x;
  if (idx >= Bb*EPROJS) return;
  int n = idx % EPROJS; int b = idx / EPROJS;
  float s = 0.f;
  #pragma unroll 4
  for (int k=0; k<H*DVv; k++){
    int h = k >> 9; int e2 = k & 511;
    s += g_cv[(size_t)(h*Bb + b)*DVv + e2] * Wo[(size_t)k*EPROJS + n];
  }
  out[idx] = s;
}

extern "C" void kernel_launch(void* const* d_in, const int* in_sizes, int n_in,
                              void* d_out, int out_size){
  const float* enc   = (const float*)d_in[0];
  // d_in[1] = enc_hs_len (unused: reference applies no masking)
  const float* dec_z = (const float*)d_in[2];
  const float* ap    = (const float*)d_in[3];
  const float* Wq    = (const float*)d_in[4];
  const float* bq    = (const float*)d_in[5];
  const float* Wk    = (const float*)d_in[6];
  const float* Wv    = (const float*)d_in[7];
  const float* gw    = (const float*)d_in[8];
  const float* gb    = (const float*)d_in[9];
  const float* Watt  = (const float*)d_in[10];
  const float* Wo    = (const float*)d_in[11];
  const float* cw0   = (const float*)d_in[12];
  const float* cw1   = (const float*)d_in[13];
  const float* cw2   = (const float*)d_in[14];
  const float* cw3   = (const float*)d_in[15];

  float* out  = (float*)d_out;
  float* wout = (out_size >= (Bb*EPROJS + H*Bb*Tt)) ? out + Bb*EPROJS : nullptr;

  const int CONV_SMEM = 1408 + 2*128*CSTR*2;   // 112000 B
  const int EN_SMEM   = 4*STGB;                // 81920 B
  cudaFuncSetAttribute(conv_mma_kernel,   cudaFuncAttributeMaxDynamicSharedMemorySize, CONV_SMEM);
  cudaFuncSetAttribute(energy_mma_kernel, cudaFuncAttributeMaxDynamicSharedMemorySize, EN_SMEM);

  enc2bf_kernel   <<<(MM*EPROJS/4 + 255)/256, 256>>>(enc);
  wconv_kernel    <<<(H*128*CTAU + 255)/256, 256>>>(cw0, cw1, cw2, cw3);
  bbf_kernel      <<<(H*DKk*KTOT + 255)/256, 256>>>(Wk, Watt);
  conv_mma_kernel <<<dim3(8, Bb, H), 256, CONV_SMEM>>>(ap);
  q_kernel        <<<(H*Bb*DKk + 255)/256, 256>>>(dec_z, Wq, bq);
  energy_mma_kernel<<<dim3(4, 250, H), 128, EN_SMEM>>>(gw);
  ereduce_kernel  <<<(H*MM + 255)/256, 256>>>(gb);
  softmax_kernel  <<<H*Bb, 256>>>(wout);
  ctx_kernel      <<<dim3(EPROJS/256, Bb), 256>>>(enc);
  cv_kernel       <<<(H*Bb*DVv + 255)/256, 256>>>(Wv);
  out_kernel      <<<(Bb*EPROJS + 255)/256, 256>>>(Wo, out);
}

// round 14
// speedup vs baseline: 4.2833x; 1.0595x over previous
#include <cuda_runtime.h>
#include <cuda_bf16.h>
#include <math.h>
#include <stdint.h>

#define H 4
#define Bb 32
#define Tt 1000
#define EPROJS 1024
#define DUNITS 1024
#define DKk 512
#define DVv 512
#define CC 100
#define MM (Bb*Tt)        // 32000
#define KTOT 1152         // 1024 (enc/Wk) + 128 (conv/Watt zero-padded)
#define NBLK 8
#define CTAU 208
#define CSTR 216
#define ESTR2 72              // energy smem row stride (bf16): 144B, conflict-free
#define STG2 (2*128*ESTR2*2)  // bytes per stage (A+B) = 36864
#define NCH64 18              // 1152/64

// ---------------- scratch ----------------
__device__ __align__(256) __nv_bfloat16 g_encbf[(size_t)MM*EPROJS];
__device__ __align__(256) __nv_bfloat16 g_convbf[(size_t)H*MM*128];
__device__ __align__(256) __nv_bfloat16 g_Bbf[(size_t)H*DKk*KTOT];
__device__ __align__(256) __nv_bfloat16 g_wconvbf[H*128*CTAU];
__device__ float g_q[H*Bb*DKk];
__device__ float g_epart[(size_t)NBLK*H*MM];
__device__ float g_e[H*MM];
__device__ float g_w[H*MM];
__device__ float g_ctx[H*Bb*EPROJS];
__device__ float g_cv[H*Bb*DVv];

// ---------------- helpers ----------------
__device__ __forceinline__ uint32_t smem_u32(const void* p){
  uint32_t a;
  asm("{ .reg .u64 t; cvta.to.shared.u64 t, %1; cvt.u32.u64 %0, t; }" : "=r"(a) : "l"(p));
  return a;
}
__device__ __forceinline__ void cp_async16(uint32_t dst, const void* src){
  asm volatile("cp.async.cg.shared.global [%0], [%1], 16;" :: "r"(dst), "l"(src) : "memory");
}
#define CP_COMMIT() asm volatile("cp.async.commit_group;" ::: "memory")
#define CP_WAIT1()  asm volatile("cp.async.wait_group 1;" ::: "memory")
#define CP_WAIT0()  asm volatile("cp.async.wait_group 0;" ::: "memory")

__device__ __forceinline__ float fast_tanh(float x){
  float y; asm("tanh.approx.f32 %0, %1;" : "=f"(y) : "f"(x)); return y;
}
__device__ __forceinline__ uint32_t pack2(float a, float b){
  __nv_bfloat162 t = __floats2bfloat162_rn(a, b);
  return *reinterpret_cast<uint32_t*>(&t);
}
__device__ __forceinline__ void ldsm4(uint32_t& r0, uint32_t& r1, uint32_t& r2, uint32_t& r3, const void* p){
  uint32_t a = (uint32_t)__cvta_generic_to_shared(p);
  asm volatile("ldmatrix.sync.aligned.m8n8.x4.shared.b16 {%0,%1,%2,%3}, [%4];"
               : "=r"(r0), "=r"(r1), "=r"(r2), "=r"(r3) : "r"(a));
}
__device__ __forceinline__ void mma16816(float* c, uint32_t a0, uint32_t a1, uint32_t a2, uint32_t a3,
                                         uint32_t b0, uint32_t b1){
  asm volatile("mma.sync.aligned.m16n8k16.row.col.f32.bf16.bf16.f32 "
               "{%0,%1,%2,%3},{%4,%5,%6,%7},{%8,%9},{%0,%1,%2,%3};"
               : "+f"(c[0]), "+f"(c[1]), "+f"(c[2]), "+f"(c[3])
               : "r"(a0), "r"(a1), "r"(a2), "r"(a3), "r"(b0), "r"(b1));
}

// ---------------- fused prep: enc->bf16, conv filters, B matrix ----------------
#define ENC_BLKS 32000     // 32,768,000 elems / 4 per thread / 256  (was 8192: BUG)
#define WCV_BLKS 416       // 106,496 / 256
#define BBF_BLKS 9216      // 2,359,296 / 256
__global__ void prep_kernel(const float* __restrict__ enc,
                            const float* __restrict__ w0, const float* __restrict__ w1,
                            const float* __restrict__ w2, const float* __restrict__ w3,
                            const float* __restrict__ Wk, const float* __restrict__ Watt){
  int bid = blockIdx.x;
  if (bid < ENC_BLKS){
    size_t i = ((size_t)bid*256 + threadIdx.x)*4;
    float4 v = *(const float4*)(enc + i);
    uint2 o; o.x = pack2(v.x, v.y); o.y = pack2(v.z, v.w);
    *(uint2*)(g_encbf + i) = o;
  } else if (bid < ENC_BLKS + WCV_BLKS){
    int idx = (bid - ENC_BLKS)*256 + threadIdx.x;
    if (idx < H*128*CTAU){
      int tau = idx % CTAU; int c = (idx/CTAU) % 128; int h = idx/(CTAU*128);
      int F = 25*(h+1), K = 2*F+1;
      const float* wb = (h==0)?w0:(h==1)?w1:(h==2)?w2:w3;
      float v = (c < CC && tau < K) ? wb[c*K + tau] : 0.f;
      g_wconvbf[idx] = __float2bfloat16_rn(v);
    }
  } else {
    int idx = (bid - ENC_BLKS - WCV_BLKS)*256 + threadIdx.x;
    int k = idx % KTOT; int n = (idx/KTOT) % DKk; int h = idx/(KTOT*DKk);
    float v = 0.f;
    if (k < EPROJS)            v = Wk[((size_t)h*EPROJS + k)*DKk + n];
    else if (k < EPROJS + CC)  v = Watt[((size_t)h*CC + (k - EPROJS))*DKk + n];
    g_Bbf[idx] = __float2bfloat16_rn(v);
  }
}

// ---------------- location conv as im2col mma GEMM -> g_convbf ----------------
__global__ __launch_bounds__(256) void conv_mma_kernel(const float* __restrict__ ap){
  extern __shared__ char dsm[];
  float* win = (float*)dsm;
  __nv_bfloat16* As = (__nv_bfloat16*)(dsm + 1408);
  __nv_bfloat16* Bs = As + 128*CSTR;

  int h = blockIdx.z, b = blockIdx.y;
  int t0 = blockIdx.x*128;
  int F = 25*(h+1);
  int tid = threadIdx.x;
  const float* arow = ap + (h*Bb + b)*Tt;

  for (int i = tid; i < 336; i += 256){
    int tt = t0 - F + i;
    win[i] = (tt >= 0 && tt < Tt) ? arow[tt] : 0.f;
  }
  const __nv_bfloat16* wsrc = g_wconvbf + h*128*CTAU;
  for (int ch = tid; ch < 128*26; ch += 256){
    int c = ch/26, t8 = (ch%26)*8;
    *(uint4*)&Bs[c*CSTR + t8] = *(const uint4*)(wsrc + c*CTAU + t8);
  }
  __syncthreads();
  for (int ch = tid; ch < 128*26; ch += 256){
    int r = ch/26, t8 = (ch%26)*8;
    uint4 v;
    v.x = pack2(win[r+t8+0], win[r+t8+1]);
    v.y = pack2(win[r+t8+2], win[r+t8+3]);
    v.z = pack2(win[r+t8+4], win[r+t8+5]);
    v.w = pack2(win[r+t8+6], win[r+t8+7]);
    *(uint4*)&As[r*CSTR + t8] = v;
  }
  __syncthreads();

  int warp = tid>>5, lane = tid&31;
  int wm = warp>>1, wn = warp&1;
  float acc[2][8][4];
  #pragma unroll
  for (int i=0;i<2;i++) for (int j=0;j<8;j++) for (int k=0;k<4;k++) acc[i][j][k]=0.f;

  #pragma unroll
  for (int k16 = 0; k16 < 13; k16++){
    uint32_t af[2][4];
    #pragma unroll
    for (int mt=0;mt<2;mt++)
      ldsm4(af[mt][0],af[mt][1],af[mt][2],af[mt][3],
        &As[(wm*32 + mt*16 + ((lane>>3)&1)*8 + (lane&7))*CSTR + k16*16 + ((lane>>4)&1)*8]);
    uint32_t bfr[8][2];
    #pragma unroll
    for (int j=0;j<4;j++){
      uint32_t r0,r1,r2,r3;
      ldsm4(r0,r1,r2,r3,
        &Bs[(wn*64 + (2*j + ((lane>>4)&1))*8 + (lane&7))*CSTR + k16*16 + ((lane>>3)&1)*8]);
      bfr[2*j][0]=r0; bfr[2*j][1]=r1; bfr[2*j+1][0]=r2; bfr[2*j+1][1]=r3;
    }
    #pragma unroll
    for (int mt=0;mt<2;mt++)
      #pragma unroll
      for (int nt=0;nt<8;nt++)
        mma16816(acc[mt][nt], af[mt][0],af[mt][1],af[mt][2],af[mt][3], bfr[nt][0], bfr[nt][1]);
  }

  int g = lane>>2, tg = lane&3;
  __nv_bfloat16* outp = g_convbf + ((size_t)h*MM + (size_t)b*Tt)*128;
  #pragma unroll
  for (int mt=0;mt<2;mt++)
    #pragma unroll
    for (int rh=0;rh<2;rh++){
      int trow = t0 + wm*32 + mt*16 + g + rh*8;
      if (trow < Tt){
        #pragma unroll
        for (int nt=0;nt<8;nt++){
          int col = wn*64 + nt*8 + tg*2;
          uint32_t pv = pack2(acc[mt][nt][rh*2+0], acc[mt][nt][rh*2+1]);
          *(uint32_t*)&outp[(size_t)trow*128 + col] = pv;
        }
      }
    }
}

// ---------------- q = dec_z @ Wq + bq ----------------
__global__ void q_kernel(const float* __restrict__ dec_z, const float* __restrict__ Wq,
                         const float* __restrict__ bq){
  int idx = blockIdx.x*blockDim.x + threadIdx.x;
  if (idx >= H*Bb*DKk) return;
  int n = idx % DKk; int b = (idx / DKk) % Bb; int h = idx / (DKk*Bb);
  const float* z  = dec_z + b*DUNITS;
  const float* wp = Wq + (size_t)h*DUNITS*DKk + n;
  float s = bq[h*DKk + n];
  #pragma unroll 4
  for (int d = 0; d < DUNITS; d++) s += z[d]*wp[(size_t)d*DKk];
  g_q[idx] = s;
}

// ---------------- fused energy GEMM: 4 warps x (64x64), K=64 chunks, frag pipelined
// grid (4, 250, 4): CTA = 128m x 128n, K = 1152 in 18 chunks of 64
__global__ __launch_bounds__(128) void energy_mma_kernel(const float* __restrict__ gw){
  extern __shared__ __align__(16) __nv_bfloat16 es[];
  uint32_t smem_base = smem_u32(es);
  int h = blockIdx.z;
  int m0 = blockIdx.y*128, n0 = blockIdx.x*128;
  int tid = threadIdx.x, warp = tid>>5, lane = tid&31;
  int wm = warp>>1, wn = warp&1;

  const __nv_bfloat16* encp  = g_encbf + (size_t)m0*EPROJS;
  const __nv_bfloat16* convp = g_convbf + ((size_t)h*MM + m0)*128;
  const __nv_bfloat16* Bp    = g_Bbf + ((size_t)h*DKk + n0)*KTOT;

  float acc[4][8][4];
  #pragma unroll
  for (int i=0;i<4;i++) for (int j=0;j<8;j++) for (int k=0;k<4;k++) acc[i][j][k]=0.f;

  auto issue_chunk = [&](int c){
    uint32_t sbase = smem_base + (uint32_t)(c & 1)*STG2;
    #pragma unroll
    for (int i=0;i<8;i++){
      int idx = tid + i*128;
      int row = idx>>3, q = idx&7;
      const __nv_bfloat16* src = (c < 16) ? (encp + (size_t)row*EPROJS + c*64 + q*8)
                                          : (convp + (size_t)row*128 + (c-16)*64 + q*8);
      cp_async16(sbase + (uint32_t)(row*ESTR2 + q*8)*2, src);
    }
    #pragma unroll
    for (int i=0;i<8;i++){
      int idx = tid + i*128;
      int row = idx>>3, q = idx&7;
      cp_async16(sbase + (uint32_t)(128*ESTR2 + row*ESTR2 + q*8)*2,
                 Bp + (size_t)row*KTOT + c*64 + q*8);
    }
  };

  issue_chunk(0); CP_COMMIT();
  issue_chunk(1); CP_COMMIT();

  uint32_t af[2][4][4], bfr[2][8][2];
  int arow_lo = ((lane>>3)&1)*8 + (lane&7);   // 0..15
  int ahalf   = ((lane>>4)&1)*8;
  int brow_lo = (lane&7);
  int bsel    = ((lane>>4)&1);
  int bhalf   = ((lane>>3)&1)*8;

  for (int c = 0; c < NCH64; c++){
    // drain: last chunk's group must be fully retired before reading
    if (c == NCH64-1) CP_WAIT0(); else CP_WAIT1();
    __syncthreads();                 // chunk c resident in stage c&1
    const __nv_bfloat16* As = es + (c & 1)*(2*128*ESTR2);
    const __nv_bfloat16* Bs = As + 128*ESTR2;

    // prime fragments for kk=0
    #pragma unroll
    for (int mt=0;mt<4;mt++)
      ldsm4(af[0][mt][0],af[0][mt][1],af[0][mt][2],af[0][mt][3],
        &As[(wm*64 + mt*16 + arow_lo)*ESTR2 + ahalf]);
    #pragma unroll
    for (int j=0;j<4;j++){
      uint32_t r0,r1,r2,r3;
      ldsm4(r0,r1,r2,r3, &Bs[(wn*64 + (2*j + bsel)*8 + brow_lo)*ESTR2 + bhalf]);
      bfr[0][2*j][0]=r0; bfr[0][2*j][1]=r1; bfr[0][2*j+1][0]=r2; bfr[0][2*j+1][1]=r3;
    }
    #pragma unroll
    for (int kk = 0; kk < 4; kk++){
      int cur = kk & 1, nxt = cur ^ 1;
      if (kk < 3){
        int ko = (kk+1)*16;
        #pragma unroll
        for (int mt=0;mt<4;mt++)
          ldsm4(af[nxt][mt][0],af[nxt][mt][1],af[nxt][mt][2],af[nxt][mt][3],
            &As[(wm*64 + mt*16 + arow_lo)*ESTR2 + ko + ahalf]);
        #pragma unroll
        for (int j=0;j<4;j++){
          uint32_t r0,r1,r2,r3;
          ldsm4(r0,r1,r2,r3, &Bs[(wn*64 + (2*j + bsel)*8 + brow_lo)*ESTR2 + ko + bhalf]);
          bfr[nxt][2*j][0]=r0; bfr[nxt][2*j][1]=r1; bfr[nxt][2*j+1][0]=r2; bfr[nxt][2*j+1][1]=r3;
        }
      }
      #pragma unroll
      for (int mt=0;mt<4;mt++)
        #pragma unroll
        for (int nt=0;nt<8;nt++)
          mma16816(acc[mt][nt], af[cur][mt][0],af[cur][mt][1],af[cur][mt][2],af[cur][mt][3],
                   bfr[cur][nt][0], bfr[cur][nt][1]);
    }
    __syncthreads();                 // all warps done reading stage c&1
    if (c + 2 < NCH64){ issue_chunk(c + 2); CP_COMMIT(); }
  }

  // epilogue: +q, tanh, * g_w, reduce over this warp's 64 cols
  int g = lane>>2, tg = lane&3;
  const float* gwp = gw + h*DKk + n0 + wn*64;
  float gwv[8][2];
  #pragma unroll
  for (int nt=0;nt<8;nt++){
    gwv[nt][0] = gwp[nt*8 + tg*2];
    gwv[nt][1] = gwp[nt*8 + tg*2 + 1];
  }
  #pragma unroll
  for (int mt=0;mt<4;mt++)
    #pragma unroll
    for (int rh=0;rh<2;rh++){
      int row = m0 + wm*64 + mt*16 + g + rh*8;
      int bb = row / Tt;
      const float* qp = g_q + (size_t)(h*Bb + bb)*DKk + n0 + wn*64;
      float psum = 0.f;
      #pragma unroll
      for (int nt=0;nt<8;nt++){
        int cb = nt*8 + tg*2;
        psum += fast_tanh(acc[mt][nt][rh*2+0] + qp[cb])   * gwv[nt][0];
        psum += fast_tanh(acc[mt][nt][rh*2+1] + qp[cb+1]) * gwv[nt][1];
      }
      psum += __shfl_xor_sync(0xffffffffu, psum, 1);
      psum += __shfl_xor_sync(0xffffffffu, psum, 2);
      if (tg == 0)
        g_epart[(size_t)(blockIdx.x*2 + wn)*(H*MM) + (size_t)h*MM + row] = psum;
    }
}

// ---------------- deterministic reduction ----------------
__global__ void ereduce_kernel(const float* __restrict__ gb){
  int idx = blockIdx.x*blockDim.x + threadIdx.x;
  if (idx >= H*MM) return;
  int h = idx / MM;
  float s = gb[h];
  #pragma unroll
  for (int j=0;j<NBLK;j++) s += g_epart[(size_t)j*(H*MM) + idx];
  g_e[idx] = s;
}

// ---------------- softmax over T per (h,b) ----------------
__global__ void softmax_kernel(float* __restrict__ wout){
  __shared__ float red[8];
  int hb = blockIdx.x;
  const float scale = 0.04419417382415922f;  // 1/sqrt(512)
  const float* ep = g_e + (size_t)hb*Tt;
  int tid = threadIdx.x;
  float v[4];
  float mx = -1e30f;
  #pragma unroll
  for (int i=0;i<4;i++){
    int t = tid + i*256;
    v[i] = (t < Tt) ? ep[t]*scale : -1e30f;
    mx = fmaxf(mx, v[i]);
  }
  #pragma unroll
  for (int o=16;o;o>>=1) mx = fmaxf(mx, __shfl_xor_sync(0xffffffffu, mx, o));
  if ((tid&31)==0) red[tid>>5] = mx;
  __syncthreads();
  mx = red[0];
  #pragma unroll
  for (int j=1;j<8;j++) mx = fmaxf(mx, red[j]);
  __syncthreads();
  float s = 0.f;
  #pragma unroll
  for (int i=0;i<4;i++){ v[i] = expf(v[i]-mx); s += v[i]; }
  #pragma unroll
  for (int o=16;o;o>>=1) s += __shfl_xor_sync(0xffffffffu, s, o);
  if ((tid&31)==0) red[tid>>5] = s;
  __syncthreads();
  s = 0.f;
  #pragma unroll
  for (int j=0;j<8;j++) s += red[j];
  float inv = 1.f/s;
  #pragma unroll
  for (int i=0;i<4;i++){
    int t = tid + i*256;
    if (t < Tt){
      float wv = v[i]*inv;
      g_w[(size_t)hb*Tt + t] = wv;
      if (wout) wout[(size_t)hb*Tt + t] = wv;
    }
  }
}

// ---------------- ctx[h,b,d] = sum_t w[h,b,t]*enc[b,t,d] (fp32) ----------------
__global__ void ctx_kernel(const float* __restrict__ enc){
  int b = blockIdx.y;
  int d = blockIdx.x*256 + threadIdx.x;
  __shared__ float ws[4][256];
  float a0=0.f,a1=0.f,a2=0.f,a3=0.f;
  for (int t0=0; t0<Tt; t0+=256){
    int n = Tt - t0; if (n > 256) n = 256;
    __syncthreads();
    if ((int)threadIdx.x < n){
      ws[0][threadIdx.x] = g_w[(size_t)(0*Bb+b)*Tt + t0 + threadIdx.x];
      ws[1][threadIdx.x] = g_w[(size_t)(1*Bb+b)*Tt + t0 + threadIdx.x];
      ws[2][threadIdx.x] = g_w[(size_t)(2*Bb+b)*Tt + t0 + threadIdx.x];
      ws[3][threadIdx.x] = g_w[(size_t)(3*Bb+b)*Tt + t0 + threadIdx.x];
    }
    __syncthreads();
    for (int tt=0; tt<n; tt++){
      float ev = enc[(size_t)(b*Tt + t0+tt)*EPROJS + d];
      a0 += ws[0][tt]*ev; a1 += ws[1][tt]*ev; a2 += ws[2][tt]*ev; a3 += ws[3][tt]*ev;
    }
  }
  g_ctx[(size_t)(0*Bb+b)*EPROJS + d] = a0;
  g_ctx[(size_t)(1*Bb+b)*EPROJS + d] = a1;
  g_ctx[(size_t)(2*Bb+b)*EPROJS + d] = a2;
  g_ctx[(size_t)(3*Bb+b)*EPROJS + d] = a3;
}

// ---------------- cv = ctx @ Wv ----------------
__global__ void cv_kernel(const float* __restrict__ Wv){
  int idx = blockIdx.x*blockDim.x + threadIdx.x;
  if (idx >= H*Bb*DVv) return;
  int n = idx % DVv; int hb = idx / DVv;
  int h = hb / Bb;
  const float* cp = g_ctx + (size_t)hb*EPROJS;
  const float* wp = Wv + (size_t)h*EPROJS*DVv + n;
  float s = 0.f;
  #pragma unroll 4
  for (int d=0; d<EPROJS; d++) s += cp[d]*wp[(size_t)d*DVv];
  g_cv[idx] = s;
}

// ---------------- out = concat_h(cv) @ Wo ----------------
__global__ void out_kernel(const float* __restrict__ Wo, float* __restrict__ out){
  int idx = blockIdx.x*blockDim.x + threadIdx.x;
  if (idx >= Bb*EPROJS) return;
  int n = idx % EPROJS; int b = idx / EPROJS;
  float s = 0.f;
  #pragma unroll 4
  for (int k=0; k<H*DVv; k++){
    int h = k >> 9; int e2 = k & 511;
    s += g_cv[(size_t)(h*Bb + b)*DVv + e2] * Wo[(size_t)k*EPROJS + n];
  }
  out[idx] = s;
}

extern "C" void kernel_launch(void* const* d_in, const int* in_sizes, int n_in,
                              void* d_out, int out_size){
  const float* enc   = (const float*)d_in[0];
  // d_in[1] = enc_hs_len (unused: reference applies no masking)
  const float* dec_z = (const float*)d_in[2];
  const float* ap    = (const float*)d_in[3];
  const float* Wq    = (const float*)d_in[4];
  const float* bq    = (const float*)d_in[5];
  const float* Wk    = (const float*)d_in[6];
  const float* Wv    = (const float*)d_in[7];
  const float* gw    = (const float*)d_in[8];
  const float* gb    = (const float*)d_in[9];
  const float* Watt  = (const float*)d_in[10];
  const float* Wo    = (const float*)d_in[11];
  const float* cw0   = (const float*)d_in[12];
  const float* cw1   = (const float*)d_in[13];
  const float* cw2   = (const float*)d_in[14];
  const float* cw3   = (const float*)d_in[15];

  float* out  = (float*)d_out;
  float* wout = (out_size >= (Bb*EPROJS + H*Bb*Tt)) ? out + Bb*EPROJS : nullptr;

  const int CONV_SMEM = 1408 + 2*128*CSTR*2;   // 112000 B
  const int EN_SMEM   = 2*STG2;                // 73728 B
  cudaFuncSetAttribute(conv_mma_kernel,   cudaFuncAttributeMaxDynamicSharedMemorySize, CONV_SMEM);
  cudaFuncSetAttribute(energy_mma_kernel, cudaFuncAttributeMaxDynamicSharedMemorySize, EN_SMEM);

  prep_kernel     <<<ENC_BLKS + WCV_BLKS + BBF_BLKS, 256>>>(enc, cw0, cw1, cw2, cw3, Wk, Watt);
  conv_mma_kernel <<<dim3(8, Bb, H), 256, CONV_SMEM>>>(ap);
  q_kernel        <<<(H*Bb*DKk + 255)/256, 256>>>(dec_z, Wq, bq);
  energy_mma_kernel<<<dim3(4, 250, H), 128, EN_SMEM>>>(gw);
  ereduce_kernel  <<<(H*MM + 255)/256, 256>>>(gb);
  softmax_kernel  <<<H*Bb, 256>>>(wout);
  ctx_kernel      <<<dim3(EPROJS/256, Bb), 256>>>(enc);
  cv_kernel       <<<(H*Bb*DVv + 255)/256, 256>>>(Wv);
  out_kernel      <<<(Bb*EPROJS + 255)/256, 256>>>(Wo, out);
}

// round 16
// speedup vs baseline: 6.4846x; 1.5139x over previous
#include <cuda_runtime.h>
#include <cuda_bf16.h>
#include <math.h>
#include <stdint.h>

#define H 4
#define Bb 32
#define Tt 1000
#define EPROJS 1024
#define DUNITS 1024
#define DKk 512
#define DVv 512
#define CC 100
#define MM (Bb*Tt)        // 32000
#define KTOT 1152
#define NBLK 8
#define CTAU 208
#define CSTR 216
#define ESTR2 72              // energy smem row stride (bf16): 144B
#define STG2 (2*128*ESTR2*2)  // 36864 B per stage
#define NCH64 18
#define TCH 8                 // ctx t-chunks
#define TLEN 125              // 1000/8

// ---------------- scratch ----------------
__device__ __align__(256) __nv_bfloat16 g_encbf[(size_t)MM*EPROJS];
__device__ __align__(256) __nv_bfloat16 g_convbf[(size_t)H*MM*128];
__device__ __align__(256) __nv_bfloat16 g_Bbf[(size_t)H*DKk*KTOT];
__device__ __align__(256) __nv_bfloat16 g_wconvbf[H*128*CTAU];
__device__ float g_q[H*Bb*DKk];
__device__ float g_epart[(size_t)NBLK*H*MM];
__device__ float g_e[H*MM];
__device__ float g_w[H*MM];
__device__ float g_ctxp[(size_t)TCH*H*Bb*EPROJS];  // split-T partials
__device__ float g_ctx[H*Bb*EPROJS];
__device__ float g_cv[H*Bb*DVv];

// ---------------- helpers ----------------
__device__ __forceinline__ uint32_t smem_u32(const void* p){
  uint32_t a;
  asm("{ .reg .u64 t; cvta.to.shared.u64 t, %1; cvt.u32.u64 %0, t; }" : "=r"(a) : "l"(p));
  return a;
}
__device__ __forceinline__ void cp_async16(uint32_t dst, const void* src){
  asm volatile("cp.async.cg.shared.global [%0], [%1], 16;" :: "r"(dst), "l"(src) : "memory");
}
#define CP_COMMIT() asm volatile("cp.async.commit_group;" ::: "memory")
#define CP_WAIT1()  asm volatile("cp.async.wait_group 1;" ::: "memory")
#define CP_WAIT0()  asm volatile("cp.async.wait_group 0;" ::: "memory")

__device__ __forceinline__ float fast_tanh(float x){
  float y; asm("tanh.approx.f32 %0, %1;" : "=f"(y) : "f"(x)); return y;
}
__device__ __forceinline__ uint32_t pack2(float a, float b){
  __nv_bfloat162 t = __floats2bfloat162_rn(a, b);
  return *reinterpret_cast<uint32_t*>(&t);
}
__device__ __forceinline__ void ldsm4(uint32_t& r0, uint32_t& r1, uint32_t& r2, uint32_t& r3, const void* p){
  uint32_t a = (uint32_t)__cvta_generic_to_shared(p);
  asm volatile("ldmatrix.sync.aligned.m8n8.x4.shared.b16 {%0,%1,%2,%3}, [%4];"
               : "=r"(r0), "=r"(r1), "=r"(r2), "=r"(r3) : "r"(a));
}
__device__ __forceinline__ void mma16816(float* c, uint32_t a0, uint32_t a1, uint32_t a2, uint32_t a3,
                                         uint32_t b0, uint32_t b1){
  asm volatile("mma.sync.aligned.m16n8k16.row.col.f32.bf16.bf16.f32 "
               "{%0,%1,%2,%3},{%4,%5,%6,%7},{%8,%9},{%0,%1,%2,%3};"
               : "+f"(c[0]), "+f"(c[1]), "+f"(c[2]), "+f"(c[3])
               : "r"(a0), "r"(a1), "r"(a2), "r"(a3), "r"(b0), "r"(b1));
}

// ---------------- fused prep: enc->bf16, conv filters, B matrix ----------------
#define ENC_BLKS 32000
#define WCV_BLKS 416
#define BBF_BLKS 9216
__global__ void prep_kernel(const float* __restrict__ enc,
                            const float* __restrict__ w0, const float* __restrict__ w1,
                            const float* __restrict__ w2, const float* __restrict__ w3,
                            const float* __restrict__ Wk, const float* __restrict__ Watt){
  int bid = blockIdx.x;
  if (bid < ENC_BLKS){
    size_t i = ((size_t)bid*256 + threadIdx.x)*4;
    float4 v = *(const float4*)(enc + i);
    uint2 o; o.x = pack2(v.x, v.y); o.y = pack2(v.z, v.w);
    *(uint2*)(g_encbf + i) = o;
  } else if (bid < ENC_BLKS + WCV_BLKS){
    int idx = (bid - ENC_BLKS)*256 + threadIdx.x;
    if (idx < H*128*CTAU){
      int tau = idx % CTAU; int c = (idx/CTAU) % 128; int h = idx/(CTAU*128);
      int F = 25*(h+1), K = 2*F+1;
      const float* wb = (h==0)?w0:(h==1)?w1:(h==2)?w2:w3;
      float v = (c < CC && tau < K) ? wb[c*K + tau] : 0.f;
      g_wconvbf[idx] = __float2bfloat16_rn(v);
    }
  } else {
    int idx = (bid - ENC_BLKS - WCV_BLKS)*256 + threadIdx.x;
    int k = idx % KTOT; int n = (idx/KTOT) % DKk; int h = idx/(KTOT*DKk);
    float v = 0.f;
    if (k < EPROJS)            v = Wk[((size_t)h*EPROJS + k)*DKk + n];
    else if (k < EPROJS + CC)  v = Watt[((size_t)h*CC + (k - EPROJS))*DKk + n];
    g_Bbf[idx] = __float2bfloat16_rn(v);
  }
}

// ---------------- location conv as im2col mma GEMM -> g_convbf ----------------
__global__ __launch_bounds__(256) void conv_mma_kernel(const float* __restrict__ ap){
  extern __shared__ char dsm[];
  float* win = (float*)dsm;
  __nv_bfloat16* As = (__nv_bfloat16*)(dsm + 1408);
  __nv_bfloat16* Bs = As + 128*CSTR;

  int h = blockIdx.z, b = blockIdx.y;
  int t0 = blockIdx.x*128;
  int F = 25*(h+1);
  int tid = threadIdx.x;
  const float* arow = ap + (h*Bb + b)*Tt;

  for (int i = tid; i < 336; i += 256){
    int tt = t0 - F + i;
    win[i] = (tt >= 0 && tt < Tt) ? arow[tt] : 0.f;
  }
  const __nv_bfloat16* wsrc = g_wconvbf + h*128*CTAU;
  for (int ch = tid; ch < 128*26; ch += 256){
    int c = ch/26, t8 = (ch%26)*8;
    *(uint4*)&Bs[c*CSTR + t8] = *(const uint4*)(wsrc + c*CTAU + t8);
  }
  __syncthreads();
  for (int ch = tid; ch < 128*26; ch += 256){
    int r = ch/26, t8 = (ch%26)*8;
    uint4 v;
    v.x = pack2(win[r+t8+0], win[r+t8+1]);
    v.y = pack2(win[r+t8+2], win[r+t8+3]);
    v.z = pack2(win[r+t8+4], win[r+t8+5]);
    v.w = pack2(win[r+t8+6], win[r+t8+7]);
    *(uint4*)&As[r*CSTR + t8] = v;
  }
  __syncthreads();

  int warp = tid>>5, lane = tid&31;
  int wm = warp>>1, wn = warp&1;
  float acc[2][8][4];
  #pragma unroll
  for (int i=0;i<2;i++) for (int j=0;j<8;j++) for (int k=0;k<4;k++) acc[i][j][k]=0.f;

  #pragma unroll
  for (int k16 = 0; k16 < 13; k16++){
    uint32_t af[2][4];
    #pragma unroll
    for (int mt=0;mt<2;mt++)
      ldsm4(af[mt][0],af[mt][1],af[mt][2],af[mt][3],
        &As[(wm*32 + mt*16 + ((lane>>3)&1)*8 + (lane&7))*CSTR + k16*16 + ((lane>>4)&1)*8]);
    uint32_t bfr[8][2];
    #pragma unroll
    for (int j=0;j<4;j++){
      uint32_t r0,r1,r2,r3;
      ldsm4(r0,r1,r2,r3,
        &Bs[(wn*64 + (2*j + ((lane>>4)&1))*8 + (lane&7))*CSTR + k16*16 + ((lane>>3)&1)*8]);
      bfr[2*j][0]=r0; bfr[2*j][1]=r1; bfr[2*j+1][0]=r2; bfr[2*j+1][1]=r3;
    }
    #pragma unroll
    for (int mt=0;mt<2;mt++)
      #pragma unroll
      for (int nt=0;nt<8;nt++)
        mma16816(acc[mt][nt], af[mt][0],af[mt][1],af[mt][2],af[mt][3], bfr[nt][0], bfr[nt][1]);
  }

  int g = lane>>2, tg = lane&3;
  __nv_bfloat16* outp = g_convbf + ((size_t)h*MM + (size_t)b*Tt)*128;
  #pragma unroll
  for (int mt=0;mt<2;mt++)
    #pragma unroll
    for (int rh=0;rh<2;rh++){
      int trow = t0 + wm*32 + mt*16 + g + rh*8;
      if (trow < Tt){
        #pragma unroll
        for (int nt=0;nt<8;nt++){
          int col = wn*64 + nt*8 + tg*2;
          uint32_t pv = pack2(acc[mt][nt][rh*2+0], acc[mt][nt][rh*2+1]);
          *(uint32_t*)&outp[(size_t)trow*128 + col] = pv;
        }
      }
    }
}

// ---------------- q = dec_z @ Wq + bq (4-acc ILP) ----------------
__global__ void q_kernel(const float* __restrict__ dec_z, const float* __restrict__ Wq,
                         const float* __restrict__ bq){
  int idx = blockIdx.x*blockDim.x + threadIdx.x;
  if (idx >= H*Bb*DKk) return;
  int n = idx % DKk; int b = (idx / DKk) % Bb; int h = idx / (DKk*Bb);
  const float* z  = dec_z + b*DUNITS;
  const float* wp = Wq + (size_t)h*DUNITS*DKk + n;
  float s0=0.f,s1=0.f,s2=0.f,s3=0.f;
  #pragma unroll 2
  for (int d = 0; d < DUNITS; d += 4){
    s0 += z[d+0]*wp[(size_t)(d+0)*DKk];
    s1 += z[d+1]*wp[(size_t)(d+1)*DKk];
    s2 += z[d+2]*wp[(size_t)(d+2)*DKk];
    s3 += z[d+3]*wp[(size_t)(d+3)*DKk];
  }
  g_q[idx] = bq[h*DKk + n] + ((s0+s1)+(s2+s3));
}

// ---------------- fused energy GEMM (unchanged from R14) ----------------
__global__ __launch_bounds__(128) void energy_mma_kernel(const float* __restrict__ gw){
  extern __shared__ __align__(16) __nv_bfloat16 es[];
  uint32_t smem_base = smem_u32(es);
  int h = blockIdx.z;
  int m0 = blockIdx.y*128, n0 = blockIdx.x*128;
  int tid = threadIdx.x, warp = tid>>5, lane = tid&31;
  int wm = warp>>1, wn = warp&1;

  const __nv_bfloat16* encp  = g_encbf + (size_t)m0*EPROJS;
  const __nv_bfloat16* convp = g_convbf + ((size_t)h*MM + m0)*128;
  const __nv_bfloat16* Bp    = g_Bbf + ((size_t)h*DKk + n0)*KTOT;

  float acc[4][8][4];
  #pragma unroll
  for (int i=0;i<4;i++) for (int j=0;j<8;j++) for (int k=0;k<4;k++) acc[i][j][k]=0.f;

  auto issue_chunk = [&](int c){
    uint32_t sbase = smem_base + (uint32_t)(c & 1)*STG2;
    #pragma unroll
    for (int i=0;i<8;i++){
      int idx = tid + i*128;
      int row = idx>>3, q = idx&7;
      const __nv_bfloat16* src = (c < 16) ? (encp + (size_t)row*EPROJS + c*64 + q*8)
                                          : (convp + (size_t)row*128 + (c-16)*64 + q*8);
      cp_async16(sbase + (uint32_t)(row*ESTR2 + q*8)*2, src);
    }
    #pragma unroll
    for (int i=0;i<8;i++){
      int idx = tid + i*128;
      int row = idx>>3, q = idx&7;
      cp_async16(sbase + (uint32_t)(128*ESTR2 + row*ESTR2 + q*8)*2,
                 Bp + (size_t)row*KTOT + c*64 + q*8);
    }
  };

  issue_chunk(0); CP_COMMIT();
  issue_chunk(1); CP_COMMIT();

  uint32_t af[2][4][4], bfr[2][8][2];
  int arow_lo = ((lane>>3)&1)*8 + (lane&7);
  int ahalf   = ((lane>>4)&1)*8;
  int brow_lo = (lane&7);
  int bsel    = ((lane>>4)&1);
  int bhalf   = ((lane>>3)&1)*8;

  for (int c = 0; c < NCH64; c++){
    if (c == NCH64-1) CP_WAIT0(); else CP_WAIT1();
    __syncthreads();
    const __nv_bfloat16* As = es + (c & 1)*(2*128*ESTR2);
    const __nv_bfloat16* Bs = As + 128*ESTR2;

    #pragma unroll
    for (int mt=0;mt<4;mt++)
      ldsm4(af[0][mt][0],af[0][mt][1],af[0][mt][2],af[0][mt][3],
        &As[(wm*64 + mt*16 + arow_lo)*ESTR2 + ahalf]);
    #pragma unroll
    for (int j=0;j<4;j++){
      uint32_t r0,r1,r2,r3;
      ldsm4(r0,r1,r2,r3, &Bs[(wn*64 + (2*j + bsel)*8 + brow_lo)*ESTR2 + bhalf]);
      bfr[0][2*j][0]=r0; bfr[0][2*j][1]=r1; bfr[0][2*j+1][0]=r2; bfr[0][2*j+1][1]=r3;
    }
    #pragma unroll
    for (int kk = 0; kk < 4; kk++){
      int cur = kk & 1, nxt = cur ^ 1;
      if (kk < 3){
        int ko = (kk+1)*16;
        #pragma unroll
        for (int mt=0;mt<4;mt++)
          ldsm4(af[nxt][mt][0],af[nxt][mt][1],af[nxt][mt][2],af[nxt][mt][3],
            &As[(wm*64 + mt*16 + arow_lo)*ESTR2 + ko + ahalf]);
        #pragma unroll
        for (int j=0;j<4;j++){
          uint32_t r0,r1,r2,r3;
          ldsm4(r0,r1,r2,r3, &Bs[(wn*64 + (2*j + bsel)*8 + brow_lo)*ESTR2 + ko + bhalf]);
          bfr[nxt][2*j][0]=r0; bfr[nxt][2*j][1]=r1; bfr[nxt][2*j+1][0]=r2; bfr[nxt][2*j+1][1]=r3;
        }
      }
      #pragma unroll
      for (int mt=0;mt<4;mt++)
        #pragma unroll
        for (int nt=0;nt<8;nt++)
          mma16816(acc[mt][nt], af[cur][mt][0],af[cur][mt][1],af[cur][mt][2],af[cur][mt][3],
                   bfr[cur][nt][0], bfr[cur][nt][1]);
    }
    __syncthreads();
    if (c + 2 < NCH64){ issue_chunk(c + 2); CP_COMMIT(); }
  }

  int g = lane>>2, tg = lane&3;
  const float* gwp = gw + h*DKk + n0 + wn*64;
  float gwv[8][2];
  #pragma unroll
  for (int nt=0;nt<8;nt++){
    gwv[nt][0] = gwp[nt*8 + tg*2];
    gwv[nt][1] = gwp[nt*8 + tg*2 + 1];
  }
  #pragma unroll
  for (int mt=0;mt<4;mt++)
    #pragma unroll
    for (int rh=0;rh<2;rh++){
      int row = m0 + wm*64 + mt*16 + g + rh*8;
      int bb = row / Tt;
      const float* qp = g_q + (size_t)(h*Bb + bb)*DKk + n0 + wn*64;
      float psum = 0.f;
      #pragma unroll
      for (int nt=0;nt<8;nt++){
        int cb = nt*8 + tg*2;
        psum += fast_tanh(acc[mt][nt][rh*2+0] + qp[cb])   * gwv[nt][0];
        psum += fast_tanh(acc[mt][nt][rh*2+1] + qp[cb+1]) * gwv[nt][1];
      }
      psum += __shfl_xor_sync(0xffffffffu, psum, 1);
      psum += __shfl_xor_sync(0xffffffffu, psum, 2);
      if (tg == 0)
        g_epart[(size_t)(blockIdx.x*2 + wn)*(H*MM) + (size_t)h*MM + row] = psum;
    }
}

// ---------------- deterministic reduction ----------------
__global__ void ereduce_kernel(const float* __restrict__ gb){
  int idx = blockIdx.x*blockDim.x + threadIdx.x;
  if (idx >= H*MM) return;
  int h = idx / MM;
  float s = gb[h];
  #pragma unroll
  for (int j=0;j<NBLK;j++) s += g_epart[(size_t)j*(H*MM) + idx];
  g_e[idx] = s;
}

// ---------------- softmax over T per (h,b) ----------------
__global__ void softmax_kernel(float* __restrict__ wout){
  __shared__ float red[8];
  int hb = blockIdx.x;
  const float scale = 0.04419417382415922f;  // 1/sqrt(512)
  const float* ep = g_e + (size_t)hb*Tt;
  int tid = threadIdx.x;
  float v[4];
  float mx = -1e30f;
  #pragma unroll
  for (int i=0;i<4;i++){
    int t = tid + i*256;
    v[i] = (t < Tt) ? ep[t]*scale : -1e30f;
    mx = fmaxf(mx, v[i]);
  }
  #pragma unroll
  for (int o=16;o;o>>=1) mx = fmaxf(mx, __shfl_xor_sync(0xffffffffu, mx, o));
  if ((tid&31)==0) red[tid>>5] = mx;
  __syncthreads();
  mx = red[0];
  #pragma unroll
  for (int j=1;j<8;j++) mx = fmaxf(mx, red[j]);
  __syncthreads();
  float s = 0.f;
  #pragma unroll
  for (int i=0;i<4;i++){ v[i] = expf(v[i]-mx); s += v[i]; }
  #pragma unroll
  for (int o=16;o;o>>=1) s += __shfl_xor_sync(0xffffffffu, s, o);
  if ((tid&31)==0) red[tid>>5] = s;
  __syncthreads();
  s = 0.f;
  #pragma unroll
  for (int j=0;j<8;j++) s += red[j];
  float inv = 1.f/s;
  #pragma unroll
  for (int i=0;i<4;i++){
    int t = tid + i*256;
    if (t < Tt){
      float wv = v[i]*inv;
      g_w[(size_t)hb*Tt + t] = wv;
      if (wout) wout[(size_t)hb*Tt + t] = wv;
    }
  }
}

// ---------------- ctx partials: split T into 8 chunks, 2048 CTAs ----------------
__global__ void ctx_part_kernel(const float* __restrict__ enc){
  int b = blockIdx.y, tc = blockIdx.z;
  int d = blockIdx.x*256 + threadIdx.x;
  int t0 = tc*TLEN;
  __shared__ float ws[4][TLEN];
  for (int i = threadIdx.x; i < 4*TLEN; i += 256){
    int hh = i / TLEN, tt = i % TLEN;
    ws[hh][tt] = g_w[(size_t)(hh*Bb+b)*Tt + t0 + tt];
  }
  __syncthreads();
  float a0=0.f,a1=0.f,a2=0.f,a3=0.f;
  const float* ep = enc + ((size_t)b*Tt + t0)*EPROJS + d;
  #pragma unroll 5
  for (int tt=0; tt<TLEN; tt++){
    float ev = ep[(size_t)tt*EPROJS];
    a0 += ws[0][tt]*ev; a1 += ws[1][tt]*ev; a2 += ws[2][tt]*ev; a3 += ws[3][tt]*ev;
  }
  size_t base = (size_t)tc*(H*Bb*EPROJS);
  g_ctxp[base + (size_t)(0*Bb+b)*EPROJS + d] = a0;
  g_ctxp[base + (size_t)(1*Bb+b)*EPROJS + d] = a1;
  g_ctxp[base + (size_t)(2*Bb+b)*EPROJS + d] = a2;
  g_ctxp[base + (size_t)(3*Bb+b)*EPROJS + d] = a3;
}

__global__ void ctx_reduce_kernel(){
  int idx = blockIdx.x*blockDim.x + threadIdx.x;
  if (idx >= H*Bb*EPROJS) return;
  float s = 0.f;
  #pragma unroll
  for (int j=0;j<TCH;j++) s += g_ctxp[(size_t)j*(H*Bb*EPROJS) + idx];
  g_ctx[idx] = s;
}

// ---------------- cv = ctx @ Wv (4-acc ILP) ----------------
__global__ void cv_kernel(const float* __restrict__ Wv){
  int idx = blockIdx.x*blockDim.x + threadIdx.x;
  if (idx >= H*Bb*DVv) return;
  int n = idx % DVv; int hb = idx / DVv;
  int h = hb / Bb;
  const float* cp = g_ctx + (size_t)hb*EPROJS;
  const float* wp = Wv + (size_t)h*EPROJS*DVv + n;
  float s0=0.f,s1=0.f,s2=0.f,s3=0.f;
  #pragma unroll 2
  for (int d=0; d<EPROJS; d+=4){
    s0 += cp[d+0]*wp[(size_t)(d+0)*DVv];
    s1 += cp[d+1]*wp[(size_t)(d+1)*DVv];
    s2 += cp[d+2]*wp[(size_t)(d+2)*DVv];
    s3 += cp[d+3]*wp[(size_t)(d+3)*DVv];
  }
  g_cv[idx] = ((s0+s1)+(s2+s3));
}

// ---------------- out = concat_h(cv) @ Wo (4-acc ILP) ----------------
__global__ void out_kernel(const float* __restrict__ Wo, float* __restrict__ out){
  int idx = blockIdx.x*blockDim.x + threadIdx.x;
  if (idx >= Bb*EPROJS) return;
  int n = idx % EPROJS; int b = idx / EPROJS;
  float s0=0.f,s1=0.f,s2=0.f,s3=0.f;
  const float* cvb = g_cv;
  #pragma unroll 2
  for (int k=0; k<H*DVv; k+=4){
    int h0 = (k+0)>>9, h1 = (k+1)>>9, h2 = (k+2)>>9, h3 = (k+3)>>9;
    s0 += cvb[(size_t)(h0*Bb + b)*DVv + ((k+0)&511)] * Wo[(size_t)(k+0)*EPROJS + n];
    s1 += cvb[(size_t)(h1*Bb + b)*DVv + ((k+1)&511)] * Wo[(size_t)(k+1)*EPROJS + n];
    s2 += cvb[(size_t)(h2*Bb + b)*DVv + ((k+2)&511)] * Wo[(size_t)(k+2)*EPROJS + n];
    s3 += cvb[(size_t)(h3*Bb + b)*DVv + ((k+3)&511)] * Wo[(size_t)(k+3)*EPROJS + n];
  }
  out[idx] = ((s0+s1)+(s2+s3));
}

extern "C" void kernel_launch(void* const* d_in, const int* in_sizes, int n_in,
                              void* d_out, int out_size){
  const float* enc   = (const float*)d_in[0];
  // d_in[1] = enc_hs_len (unused: reference applies no masking)
  const float* dec_z = (const float*)d_in[2];
  const float* ap    = (const float*)d_in[3];
  const float* Wq    = (const float*)d_in[4];
  const float* bq    = (const float*)d_in[5];
  const float* Wk    = (const float*)d_in[6];
  const float* Wv    = (const float*)d_in[7];
  const float* gw    = (const float*)d_in[8];
  const float* gb    = (const float*)d_in[9];
  const float* Watt  = (const float*)d_in[10];
  const float* Wo    = (const float*)d_in[11];
  const float* cw0   = (const float*)d_in[12];
  const float* cw1   = (const float*)d_in[13];
  const float* cw2   = (const float*)d_in[14];
  const float* cw3   = (const float*)d_in[15];

  float* out  = (float*)d_out;
  float* wout = (out_size >= (Bb*EPROJS + H*Bb*Tt)) ? out + Bb*EPROJS : nullptr;

  const int CONV_SMEM = 1408 + 2*128*CSTR*2;   // 112000 B
  const int EN_SMEM   = 2*STG2;                // 73728 B
  cudaFuncSetAttribute(conv_mma_kernel,   cudaFuncAttributeMaxDynamicSharedMemorySize, CONV_SMEM);
  cudaFuncSetAttribute(energy_mma_kernel, cudaFuncAttributeMaxDynamicSharedMemorySize, EN_SMEM);

  prep_kernel      <<<ENC_BLKS + WCV_BLKS + BBF_BLKS, 256>>>(enc, cw0, cw1, cw2, cw3, Wk, Watt);
  conv_mma_kernel  <<<dim3(8, Bb, H), 256, CONV_SMEM>>>(ap);
  q_kernel         <<<(H*Bb*DKk + 255)/256, 256>>>(dec_z, Wq, bq);
  energy_mma_kernel<<<dim3(4, 250, H), 128, EN_SMEM>>>(gw);
  ereduce_kernel   <<<(H*MM + 255)/256, 256>>>(gb);
  softmax_kernel   <<<H*Bb, 256>>>(wout);
  ctx_part_kernel  <<<dim3(EPROJS/256, Bb, TCH), 256>>>(enc);
  ctx_reduce_kernel<<<(H*Bb*EPROJS + 255)/256, 256>>>();
  cv_kernel        <<<(H*Bb*DVv + 255)/256, 256>>>(Wv);
  out_kernel       <<<(Bb*EPROJS + 255)/256, 256>>>(Wo, out);
}